// round 4
// baseline (speedup 1.0000x reference)
#include <cuda_runtime.h>
#include <math.h>
#include <stdint.h>

#define BATCH 16
#define KTOK  1024
#define DD    768
#define SEM   384
#define STRD  384
#define NB    128
#define NSTEP (KTOK/NB)

// ---------------- device scratch (bss, no runtime allocation) ----------------
__device__ float  g_ei [BATCH*KTOK*SEM];
__device__ float  g_di [BATCH*KTOK*STRD];
__device__ float  g_uj [BATCH*KTOK*STRD];
__device__ float  g_uk [BATCH*KTOK*STRD];
__device__ float  g_v  [BATCH*KTOK*STRD];
__device__ float  g_A  [(size_t)BATCH*KTOK*KTOK];   // raw scores, then normalized A
__device__ float  g_aik[(size_t)BATCH*KTOK*KTOK];
__device__ float  g_g  [BATCH*KTOK];                // raw root scores (pre-exp)
__device__ float  g_cm [BATCH*KTOK];                // per-column max
__device__ float  g_fid[BATCH*KTOK];                // normalized root weight exp(g-m)
__device__ double g_cs [BATCH*KTOK];                // column sums (fp64)
__device__ double g_Md [(size_t)BATCH*KTOK*KTOK];
__device__ double g_Invd[(size_t)BATCH*KTOK*KTOK];
__device__ double g_Wd [BATCH*KTOK*NB];
__device__ double g_Pvd[BATCH*NB*NB];
__device__ double g_RMd[BATCH*NB*KTOK];
__device__ double g_RId[BATCH*NB*(KTOK+NB)];
__device__ float  g_si [BATCH*KTOK*SEM];
__device__ float  g_ci [BATCH*KTOK*SEM];

// ---------------- elementwise kernels ----------------
__global__ void split_kernel(const float* __restrict__ x,
                             float* __restrict__ ei, float* __restrict__ di) {
    int i = blockIdx.x * blockDim.x + threadIdx.x;
    if (i >= BATCH*KTOK*SEM) return;
    int c  = i % SEM;
    int bk = i / SEM;
    const float* xr = x + (size_t)bk * DD;
    ei[i] = xr[c < 192 ? c       : c + 192];
    di[i] = xr[c < 192 ? c + 192 : c + 384];
}

// raw root score g = d @ fi_w (NO exp here)
__global__ void fi_kernel(const float* __restrict__ di,
                          const float* __restrict__ fw,
                          float* __restrict__ g) {
    int row  = blockIdx.x * 8 + (threadIdx.x >> 5);
    int lane = threadIdx.x & 31;
    if (row >= BATCH*KTOK) return;
    const float* d = di + (size_t)row * STRD;
    float s = 0.f;
    for (int c = lane; c < STRD; c += 32) s += d[c] * fw[c];
    #pragma unroll
    for (int o = 16; o; o >>= 1) s += __shfl_xor_sync(0xffffffffu, s, o);
    if (lane == 0) g[row] = s;
}

// m_k = max(g_k, max_{j!=k} S[j,k])
__global__ void colmax_kernel(const float* __restrict__ S,
                              const float* __restrict__ g,
                              float* __restrict__ cm) {
    int i = blockIdx.x * blockDim.x + threadIdx.x;
    if (i >= BATCH*KTOK) return;
    int b = i / KTOK, k = i % KTOK;
    const float* Sb = S + (size_t)b*KTOK*KTOK + k;
    float m = g[i];
    for (int j = 0; j < KTOK; j++) {
        if (j == k) continue;
        float v = Sb[(size_t)j*KTOK];
        m = fmaxf(m, v);
    }
    cm[i] = m;
}

// A[j,k] = (j==k) ? 0 : exp(S - m_k)  (in place over S)
__global__ void normA_kernel(float* __restrict__ S, const float* __restrict__ cm) {
    size_t i = (size_t)blockIdx.x * blockDim.x + threadIdx.x;
    if (i >= (size_t)BATCH*KTOK*KTOK) return;
    int k = (int)(i % KTOK);
    size_t t = i / KTOK;
    int j = (int)(t % KTOK);
    int b = (int)(t / KTOK);
    S[i] = (j == k) ? 0.f : expf(S[i] - cm[b*KTOK + k]);
}

__global__ void fid_kernel(const float* __restrict__ g, const float* __restrict__ cm,
                           float* __restrict__ fid) {
    int i = blockIdx.x * blockDim.x + threadIdx.x;
    if (i >= BATCH*KTOK) return;
    fid[i] = expf(g[i] - cm[i]);
}

__global__ void colsum_kernel(const float* __restrict__ A, double* __restrict__ cs) {
    int i = blockIdx.x * blockDim.x + threadIdx.x;
    if (i >= BATCH*KTOK) return;
    int b = i / KTOK, k = i % KTOK;
    const float* Ab = A + (size_t)b*KTOK*KTOK + k;
    double s = 0.0;
    for (int j = 0; j < KTOK; j++) s += (double)Ab[(size_t)j*KTOK];
    cs[i] = s;
}

__global__ void build_kernel(const float* __restrict__ A,
                             const float* __restrict__ fid,
                             const double* __restrict__ cs,
                             double* __restrict__ M, double* __restrict__ Inv) {
    size_t i = (size_t)blockIdx.x * blockDim.x + threadIdx.x;
    if (i >= (size_t)BATCH*KTOK*KTOK) return;
    int k = (int)(i % KTOK);
    size_t t = i / KTOK;
    int j = (int)(t % KTOK);
    int b = (int)(t / KTOK);
    double v;
    if (j == 0) v = (double)fid[b*KTOK + k];
    else        v = -(double)A[i] + (j == k ? cs[b*KTOK + k] : 0.0);
    M[i]   = v;
    Inv[i] = (j == k) ? 1.0 : 0.0;
}

__global__ void copyw_kernel(const double* __restrict__ M, double* __restrict__ W, int k0) {
    int i = blockIdx.x * blockDim.x + threadIdx.x;
    if (i >= BATCH*KTOK*NB) return;
    int t = i % NB;
    int r = (i / NB) % KTOK;
    int b = i / (NB*KTOK);
    double w = M[(size_t)b*KTOK*KTOK + (size_t)r*KTOK + k0 + t];
    if (r == k0 + t) w -= 1.0;
    W[i] = w;
}

// in-smem fp64 Gauss-Jordan inversion of the 128x128 pivot block
__global__ void pivot_inv_kernel(const double* __restrict__ M,
                                 double* __restrict__ Pinv, int k0) {
    extern __shared__ double P[];   // NB x (NB+1)
    int b = blockIdx.x;
    const double* Mb = M + (size_t)b*KTOK*KTOK;
    for (int i = threadIdx.x; i < NB*NB; i += blockDim.x) {
        int r = i >> 7, c = i & 127;
        P[r*129 + c] = Mb[(size_t)(k0 + r)*KTOK + k0 + c];
    }
    __syncthreads();
    int r  = threadIdx.x >> 2;          // 512 threads -> 4 threads per row
    int c0 = (threadIdx.x & 3) * 32;
    for (int j = 0; j < NB; j++) {
        double pv   = P[j*129 + j];
        double pinv = 1.0 / pv;
        double f    = P[r*129 + j];
        __syncthreads();
        if (r == j) {
            for (int c = c0; c < c0 + 32; c++)
                P[j*129 + c] = (c == j) ? pinv : P[j*129 + c] * pinv;
        }
        __syncthreads();
        if (r != j) {
            for (int c = c0; c < c0 + 32; c++) {
                double nv = (c == j) ? (-f * pinv)
                                     : (P[r*129 + c] - f * P[j*129 + c]);
                P[r*129 + c] = nv;
            }
        }
        __syncthreads();
    }
    for (int i = threadIdx.x; i < NB*NB; i += blockDim.x) {
        int rr = i >> 7, cc = i & 127;
        Pinv[(size_t)b*NB*NB + i] = P[rr*129 + cc];
    }
}

// edge marginals (fp64 inverse) + transposed store of a_ki into output buffer
__global__ void marginals_kernel(const float* __restrict__ A,
                                 const double* __restrict__ Inv,
                                 float* __restrict__ aik,
                                 float* __restrict__ out_a) {
    __shared__ double tInv[32][33];
    __shared__ float  tV[32][33];
    __shared__ double dk[32];
    int b  = blockIdx.z;
    int k0 = blockIdx.x * 32;
    int j0 = blockIdx.y * 32;
    const double* Ib = Inv + (size_t)b*KTOK*KTOK;
    const float*  Ab = A   + (size_t)b*KTOK*KTOK;
    int tx = threadIdx.x, ty = threadIdx.y;
    #pragma unroll
    for (int s = 0; s < 4; s++) {
        int kk = ty + 8*s;
        tInv[kk][tx] = Ib[(size_t)(k0 + kk)*KTOK + j0 + tx];
    }
    if (ty == 0) dk[tx] = Ib[(size_t)(k0 + tx)*KTOK + k0 + tx];
    __syncthreads();
    #pragma unroll
    for (int s = 0; s < 4; s++) {
        int jj = ty + 8*s;
        int j = j0 + jj, k = k0 + tx;
        double a = (double)Ab[(size_t)j*KTOK + k];
        double v = ((k != 0) ? a * dk[tx] : 0.0)
                 - ((j != 0) ? a * tInv[tx][jj] : 0.0);
        float vf = (float)v;
        aik[(size_t)b*KTOK*KTOK + (size_t)j*KTOK + k] = vf;
        tV[jj][tx] = vf;
    }
    __syncthreads();
    #pragma unroll
    for (int s = 0; s < 4; s++) {
        int kk = ty + 8*s;
        out_a[(size_t)b*KTOK*(KTOK+1) + (size_t)(k0 + kk)*(KTOK+1) + (j0 + tx) + 1]
            = tV[tx][kk];
    }
}

__global__ void d0_kernel(const float* __restrict__ fid,
                          const double* __restrict__ Inv,
                          float* __restrict__ out_a) {
    int i = blockIdx.x * blockDim.x + threadIdx.x;
    if (i >= BATCH*KTOK) return;
    int b = i / KTOK, k = i % KTOK;
    out_a[(size_t)b*KTOK*(KTOK+1) + (size_t)k*(KTOK+1)]
        = (float)((double)fid[i] * Inv[(size_t)b*KTOK*KTOK + (size_t)k*KTOK]);
}

__global__ void rank1_kernel(const float* __restrict__ out_a,
                             const float* __restrict__ exparam,
                             float* __restrict__ si) {
    int i = blockIdx.x * blockDim.x + threadIdx.x;
    if (i >= BATCH*KTOK*SEM) return;
    int c  = i % SEM;
    int bj = i / SEM;
    int b = bj / KTOK, j = bj % KTOK;
    float a0 = out_a[(size_t)b*KTOK*(KTOK+1) + (size_t)j*(KTOK+1)];
    si[i] += a0 * exparam[c];
}

// ---------------- generic strided batched fp32 GEMM ----------------
#define FLAG_BIAS  1
#define FLAG_TANH  2

__global__ __launch_bounds__(256)
void gemm_kernel(const float* __restrict__ A, const float* __restrict__ B,
                 float* __restrict__ C, const float* __restrict__ bias,
                 int M, int N, int Kd,
                 long long sAb, int sAm, int sAk,
                 long long sBb, int sBk, int sBn,
                 long long sCb, int sCm,
                 float alpha, float beta, int flags) {
    __shared__ float As[16][68];
    __shared__ float Bs[16][68];
    int b = blockIdx.z;
    A += (size_t)b * sAb;
    B += (size_t)b * sBb;
    C += (size_t)b * sCb;
    int m0 = blockIdx.y * 64, n0 = blockIdx.x * 64;
    int tid = threadIdx.x;
    int tx = tid & 15, ty = tid >> 4;
    float acc[4][4] = {};
    for (int k0 = 0; k0 < Kd; k0 += 16) {
        if (sAk == 1) {                 // contiguous in K
            int kk = tid & 15, mm = tid >> 4;
            #pragma unroll
            for (int p = 0; p < 4; p++) {
                int m = mm + p*16;
                int gm = m0 + m, gk = k0 + kk;
                As[kk][m] = (gm < M && gk < Kd) ? A[(size_t)gm*sAm + gk] : 0.f;
            }
        } else {
            int mm = tid & 63, kk = tid >> 6;
            #pragma unroll
            for (int p = 0; p < 4; p++) {
                int k = kk + p*4;
                int gm = m0 + mm, gk = k0 + k;
                As[k][mm] = (gm < M && gk < Kd) ? A[(size_t)gm*sAm + (size_t)gk*sAk] : 0.f;
            }
        }
        if (sBn == 1) {
            int nn = tid & 63, kk = tid >> 6;
            #pragma unroll
            for (int p = 0; p < 4; p++) {
                int k = kk + p*4;
                int gn = n0 + nn, gk = k0 + k;
                Bs[k][nn] = (gn < N && gk < Kd) ? B[(size_t)gk*sBk + gn] : 0.f;
            }
        } else {
            int kk = tid & 15, nn = tid >> 4;
            #pragma unroll
            for (int p = 0; p < 4; p++) {
                int n = nn + p*16;
                int gn = n0 + n, gk = k0 + kk;
                Bs[kk][n] = (gn < N && gk < Kd) ? B[(size_t)gk*sBk + (size_t)gn*sBn] : 0.f;
            }
        }
        __syncthreads();
        #pragma unroll
        for (int kk = 0; kk < 16; kk++) {
            float4 a4 = *(const float4*)&As[kk][ty*4];
            float4 b4 = *(const float4*)&Bs[kk][tx*4];
            float a[4] = {a4.x, a4.y, a4.z, a4.w};
            float bb[4] = {b4.x, b4.y, b4.z, b4.w};
            #pragma unroll
            for (int i2 = 0; i2 < 4; i2++)
                #pragma unroll
                for (int j2 = 0; j2 < 4; j2++)
                    acc[i2][j2] += a[i2] * bb[j2];
        }
        __syncthreads();
    }
    #pragma unroll
    for (int i2 = 0; i2 < 4; i2++) {
        int gm = m0 + ty*4 + i2;
        if (gm >= M) continue;
        #pragma unroll
        for (int j2 = 0; j2 < 4; j2++) {
            int gn = n0 + tx*4 + j2;
            if (gn >= N) continue;
            size_t ci = (size_t)gm * sCm + gn;
            float v = alpha * acc[i2][j2];
            if (beta != 0.f)       v += beta * C[ci];
            if (flags & FLAG_BIAS) v += bias[gn];
            if (flags & FLAG_TANH) v = tanhf(v);
            C[ci] = v;
        }
    }
}

static inline void launch_gemm(const float* A, const float* B, float* C,
                               const float* bias,
                               int M, int N, int Kd,
                               long long sAb, int sAm, int sAk,
                               long long sBb, int sBk, int sBn,
                               long long sCb, int sCm,
                               float alpha, float beta, int flags, int batch) {
    dim3 g((N + 63) / 64, (M + 63) / 64, batch);
    gemm_kernel<<<g, 256>>>(A, B, C, bias, M, N, Kd,
                            sAb, sAm, sAk, sBb, sBk, sBn, sCb, sCm,
                            alpha, beta, flags);
}

// ---------------- fp64 batched GEMM (A contiguous-in-K, B contiguous-in-N) ----------------
__global__ __launch_bounds__(256)
void dgemm_kernel(const double* __restrict__ A, const double* __restrict__ B,
                  double* __restrict__ C,
                  int M, int N, int Kd,
                  long long sAb, int sAm,
                  long long sBb, int sBk,
                  long long sCb, int sCm,
                  double alpha, double beta) {
    __shared__ double As[16][65];
    __shared__ double Bs[16][65];
    int b = blockIdx.z;
    A += (size_t)b * sAb;
    B += (size_t)b * sBb;
    C += (size_t)b * sCb;
    int m0 = blockIdx.y * 64, n0 = blockIdx.x * 64;
    int tid = threadIdx.x;
    int tx = tid & 15, ty = tid >> 4;
    double acc[4][4] = {};
    for (int k0 = 0; k0 < Kd; k0 += 16) {
        {
            int kk = tid & 15, mm = tid >> 4;
            #pragma unroll
            for (int p = 0; p < 4; p++) {
                int m = mm + p*16;
                int gm = m0 + m, gk = k0 + kk;
                As[kk][m] = (gm < M && gk < Kd) ? A[(size_t)gm*sAm + gk] : 0.0;
            }
        }
        {
            int nn = tid & 63, kk = tid >> 6;
            #pragma unroll
            for (int p = 0; p < 4; p++) {
                int k = kk + p*4;
                int gn = n0 + nn, gk = k0 + k;
                Bs[k][nn] = (gn < N && gk < Kd) ? B[(size_t)gk*sBk + gn] : 0.0;
            }
        }
        __syncthreads();
        #pragma unroll
        for (int kk = 0; kk < 16; kk++) {
            double a[4], bb[4];
            #pragma unroll
            for (int i2 = 0; i2 < 4; i2++) a[i2]  = As[kk][ty*4 + i2];
            #pragma unroll
            for (int j2 = 0; j2 < 4; j2++) bb[j2] = Bs[kk][tx*4 + j2];
            #pragma unroll
            for (int i2 = 0; i2 < 4; i2++)
                #pragma unroll
                for (int j2 = 0; j2 < 4; j2++)
                    acc[i2][j2] += a[i2] * bb[j2];
        }
        __syncthreads();
    }
    #pragma unroll
    for (int i2 = 0; i2 < 4; i2++) {
        int gm = m0 + ty*4 + i2;
        if (gm >= M) continue;
        #pragma unroll
        for (int j2 = 0; j2 < 4; j2++) {
            int gn = n0 + tx*4 + j2;
            if (gn >= N) continue;
            size_t ci = (size_t)gm * sCm + gn;
            double v = alpha * acc[i2][j2];
            if (beta != 0.0) v += beta * C[ci];
            C[ci] = v;
        }
    }
}

static inline void launch_dgemm(const double* A, const double* B, double* C,
                                int M, int N, int Kd,
                                long long sAb, int sAm,
                                long long sBb, int sBk,
                                long long sCb, int sCm,
                                double alpha, double beta, int batch) {
    dim3 g((N + 63) / 64, (M + 63) / 64, batch);
    dgemm_kernel<<<g, 256>>>(A, B, C, M, N, Kd,
                             sAb, sAm, sBb, sBk, sCb, sCm, alpha, beta);
}

// ---------------- driver ----------------
extern "C" void kernel_launch(void* const* d_in, const int* in_sizes, int n_in,
                              void* d_out, int out_size) {
    const float* x       = (const float*)d_in[0];
    const float* Wp_w    = (const float*)d_in[1];
    const float* Wp_b    = (const float*)d_in[2];
    const float* Wc_w    = (const float*)d_in[3];
    const float* Wc_b    = (const float*)d_in[4];
    const float* fi_w    = (const float*)d_in[5];
    const float* Wa_w    = (const float*)d_in[6];
    const float* exparam = (const float*)d_in[7];
    const float* Wr_w    = (const float*)d_in[8];
    const float* Wr_b    = (const float*)d_in[9];

    float* out_r = (float*)d_out;
    float* out_a = out_r + (size_t)BATCH*KTOK*SEM;

    float  *ei, *di, *uj, *uk, *vv, *Am, *aik, *gg, *cm, *fid, *si, *ci;
    double *cs, *Md, *Invd, *Wd, *Pvd, *RMd, *RId;
    cudaGetSymbolAddress((void**)&ei,   g_ei);
    cudaGetSymbolAddress((void**)&di,   g_di);
    cudaGetSymbolAddress((void**)&uj,   g_uj);
    cudaGetSymbolAddress((void**)&uk,   g_uk);
    cudaGetSymbolAddress((void**)&vv,   g_v);
    cudaGetSymbolAddress((void**)&Am,   g_A);
    cudaGetSymbolAddress((void**)&aik,  g_aik);
    cudaGetSymbolAddress((void**)&gg,   g_g);
    cudaGetSymbolAddress((void**)&cm,   g_cm);
    cudaGetSymbolAddress((void**)&fid,  g_fid);
    cudaGetSymbolAddress((void**)&si,   g_si);
    cudaGetSymbolAddress((void**)&ci,   g_ci);
    cudaGetSymbolAddress((void**)&cs,   g_cs);
    cudaGetSymbolAddress((void**)&Md,   g_Md);
    cudaGetSymbolAddress((void**)&Invd, g_Invd);
    cudaGetSymbolAddress((void**)&Wd,   g_Wd);
    cudaGetSymbolAddress((void**)&Pvd,  g_Pvd);
    cudaGetSymbolAddress((void**)&RMd,  g_RMd);
    cudaGetSymbolAddress((void**)&RId,  g_RId);

    cudaFuncSetAttribute(pivot_inv_kernel,
                         cudaFuncAttributeMaxDynamicSharedMemorySize, NB*(NB+1)*8);

    // 1) semantic/structural split
    split_kernel<<<(BATCH*KTOK*SEM + 255)/256, 256>>>(x, ei, di);

    // 2) u_j = tanh(d W_p + b), u_k = tanh(d W_c + b)
    launch_gemm(di, Wp_w, uj, Wp_b, BATCH*KTOK, STRD, STRD,
                0, STRD, 1, 0, STRD, 1, 0, STRD, 1.f, 0.f, FLAG_BIAS|FLAG_TANH, 1);
    launch_gemm(di, Wc_w, uk, Wc_b, BATCH*KTOK, STRD, STRD,
                0, STRD, 1, 0, STRD, 1, 0, STRD, 1.f, 0.f, FLAG_BIAS|FLAG_TANH, 1);

    // 3) v = u_k @ Wa^T
    launch_gemm(uk, Wa_w, vv, nullptr, BATCH*KTOK, STRD, STRD,
                0, STRD, 1, 0, 1, STRD, 0, STRD, 1.f, 0.f, 0, 1);

    // 4) raw root scores g = d @ fi_w
    fi_kernel<<<(BATCH*KTOK + 7)/8, 256>>>(di, fi_w, gg);

    // 5) raw bilinear scores S = u_j v^T  (batched NT GEMM)
    launch_gemm(uj, vv, Am, nullptr, KTOK, KTOK, STRD,
                (long long)KTOK*STRD, STRD, 1,
                (long long)KTOK*STRD, 1, STRD,
                (long long)KTOK*KTOK, KTOK, 1.f, 0.f, 0, BATCH);

    // 6) per-column max normalization (tree marginals are column-scale invariant)
    colmax_kernel<<<(BATCH*KTOK + 255)/256, 256>>>(Am, gg, cm);
    normA_kernel<<<(unsigned)(((size_t)BATCH*KTOK*KTOK + 255)/256), 256>>>(Am, cm);
    fid_kernel<<<(BATCH*KTOK + 255)/256, 256>>>(gg, cm, fid);
    colsum_kernel<<<(BATCH*KTOK + 255)/256, 256>>>(Am, cs);

    // 7) Laplacian in fp64 + identity
    build_kernel<<<(unsigned)(((size_t)BATCH*KTOK*KTOK + 255)/256), 256>>>(Am, fid, cs, Md, Invd);

    // 8) fp64 blocked Gauss-Jordan inversion: Invd = Md^{-1}
    for (int s = 0; s < NSTEP; s++) {
        int k0 = s * NB;
        copyw_kernel<<<(BATCH*KTOK*NB + 255)/256, 256>>>(Md, Wd, k0);
        pivot_inv_kernel<<<BATCH, 512, NB*(NB+1)*8>>>(Md, Pvd, k0);
        // R_M = P^-1 @ M[pivot rows, k0:]
        launch_dgemm(Pvd, Md + (size_t)k0*KTOK + k0, RMd, NB, KTOK - k0, NB,
                     (long long)NB*NB, NB,
                     (long long)KTOK*KTOK, KTOK,
                     (long long)NB*KTOK, KTOK, 1.0, 0.0, BATCH);
        // R_I = P^-1 @ Inv[pivot rows, :k0+NB]
        launch_dgemm(Pvd, Invd + (size_t)k0*KTOK, RId, NB, k0 + NB, NB,
                     (long long)NB*NB, NB,
                     (long long)KTOK*KTOK, KTOK,
                     (long long)NB*(KTOK+NB), KTOK+NB, 1.0, 0.0, BATCH);
        // M[:, k0:] -= W @ R_M
        launch_dgemm(Wd, RMd, Md + k0, KTOK, KTOK - k0, NB,
                     (long long)KTOK*NB, NB,
                     (long long)NB*KTOK, KTOK,
                     (long long)KTOK*KTOK, KTOK, -1.0, 1.0, BATCH);
        // Inv[:, :k0+NB] -= W @ R_I
        launch_dgemm(Wd, RId, Invd, KTOK, k0 + NB, NB,
                     (long long)KTOK*NB, NB,
                     (long long)NB*(KTOK+NB), KTOK+NB,
                     (long long)KTOK*KTOK, KTOK, -1.0, 1.0, BATCH);
    }

    // 9) edge marginals a_ik, transposed a_ki into output, root column d0
    marginals_kernel<<<dim3(KTOK/32, KTOK/32, BATCH), dim3(32, 8)>>>(Am, Invd, aik, out_a);
    d0_kernel<<<(BATCH*KTOK + 255)/256, 256>>>(fid, Invd, out_a);

    // 10) si = a_ki[:,:,1:] @ e_i + a_ki[:,:,0] x exparam
    launch_gemm(out_a + 1, ei, si, nullptr, KTOK, SEM, KTOK,
                (long long)KTOK*(KTOK+1), KTOK+1, 1,
                (long long)KTOK*SEM, SEM, 1,
                (long long)KTOK*SEM, SEM, 1.f, 0.f, 0, BATCH);
    rank1_kernel<<<(BATCH*KTOK*SEM + 255)/256, 256>>>(out_a, exparam, si);

    // 11) ci = a_ik @ e_i
    launch_gemm(aik, ei, ci, nullptr, KTOK, SEM, KTOK,
                (long long)KTOK*KTOK, KTOK, 1,
                (long long)KTOK*SEM, SEM, 1,
                (long long)KTOK*SEM, SEM, 1.f, 0.f, 0, BATCH);

    // 12) r = tanh([e|si|ci] @ Wr + b)   as 3 accumulating GEMMs
    launch_gemm(ei, Wr_w, out_r, nullptr, BATCH*KTOK, SEM, STRD,
                0, SEM, 1, 0, SEM, 1, 0, SEM, 1.f, 0.f, 0, 1);
    launch_gemm(si, Wr_w + (size_t)384*384, out_r, nullptr, BATCH*KTOK, SEM, STRD,
                0, SEM, 1, 0, SEM, 1, 0, SEM, 1.f, 1.f, 0, 1);
    launch_gemm(ci, Wr_w + (size_t)768*384, out_r, Wr_b, BATCH*KTOK, SEM, STRD,
                0, SEM, 1, 0, SEM, 1, 0, SEM, 1.f, 1.f, FLAG_BIAS|FLAG_TANH, 1);
}

// round 5
// speedup vs baseline: 3.9076x; 3.9076x over previous
#include <cuda_runtime.h>
#include <math.h>
#include <stdint.h>

#define BATCH 16
#define KTOK  1024
#define DD    768
#define SEM   384
#define STRD  384
#define NB    128
#define NSTEP (KTOK/NB)

// ---------------- device scratch (bss, no runtime allocation) ----------------
__device__ float  g_ei [BATCH*KTOK*SEM];
__device__ float  g_di [BATCH*KTOK*STRD];
__device__ float  g_uj [BATCH*KTOK*STRD];
__device__ float  g_uk [BATCH*KTOK*STRD];
__device__ float  g_v  [BATCH*KTOK*STRD];
__device__ float  g_A  [(size_t)BATCH*KTOK*KTOK];   // raw scores, then normalized A
__device__ float  g_aik[(size_t)BATCH*KTOK*KTOK];
__device__ float  g_g  [BATCH*KTOK];                // raw root scores (pre-exp)
__device__ float  g_cm [BATCH*KTOK];                // per-column max
__device__ float  g_fid[BATCH*KTOK];                // normalized root weight exp(g-m)
__device__ float  g_cs [BATCH*KTOK];                // column sums (fp64-accumulated)
__device__ float  g_Mf [(size_t)BATCH*KTOK*KTOK];
__device__ float  g_If [(size_t)BATCH*KTOK*KTOK];
__device__ float  g_Wf [BATCH*KTOK*NB];
__device__ float  g_Pvf[BATCH*NB*NB];
__device__ float  g_RMf[BATCH*NB*KTOK];
__device__ float  g_RIf[BATCH*NB*(KTOK+NB)];
__device__ float  g_si [BATCH*KTOK*SEM];
__device__ float  g_ci [BATCH*KTOK*SEM];

// ---------------- elementwise kernels ----------------
__global__ void split_kernel(const float* __restrict__ x,
                             float* __restrict__ ei, float* __restrict__ di) {
    int i = blockIdx.x * blockDim.x + threadIdx.x;
    if (i >= BATCH*KTOK*SEM) return;
    int c  = i % SEM;
    int bk = i / SEM;
    const float* xr = x + (size_t)bk * DD;
    ei[i] = xr[c < 192 ? c       : c + 192];
    di[i] = xr[c < 192 ? c + 192 : c + 384];
}

// raw root score g = d @ fi_w (NO exp here)
__global__ void fi_kernel(const float* __restrict__ di,
                          const float* __restrict__ fw,
                          float* __restrict__ g) {
    int row  = blockIdx.x * 8 + (threadIdx.x >> 5);
    int lane = threadIdx.x & 31;
    if (row >= BATCH*KTOK) return;
    const float* d = di + (size_t)row * STRD;
    float s = 0.f;
    for (int c = lane; c < STRD; c += 32) s += d[c] * fw[c];
    #pragma unroll
    for (int o = 16; o; o >>= 1) s += __shfl_xor_sync(0xffffffffu, s, o);
    if (lane == 0) g[row] = s;
}

// m_k = max(g_k, max_{j!=k} S[j,k])
__global__ void colmax_kernel(const float* __restrict__ S,
                              const float* __restrict__ g,
                              float* __restrict__ cm) {
    int i = blockIdx.x * blockDim.x + threadIdx.x;
    if (i >= BATCH*KTOK) return;
    int b = i / KTOK, k = i % KTOK;
    const float* Sb = S + (size_t)b*KTOK*KTOK + k;
    float m = g[i];
    for (int j = 0; j < KTOK; j++) {
        if (j == k) continue;
        float v = Sb[(size_t)j*KTOK];
        m = fmaxf(m, v);
    }
    cm[i] = m;
}

// A[j,k] = (j==k) ? 0 : exp(S - m_k)  (in place over S)
__global__ void normA_kernel(float* __restrict__ S, const float* __restrict__ cm) {
    size_t i = (size_t)blockIdx.x * blockDim.x + threadIdx.x;
    if (i >= (size_t)BATCH*KTOK*KTOK) return;
    int k = (int)(i % KTOK);
    size_t t = i / KTOK;
    int j = (int)(t % KTOK);
    int b = (int)(t / KTOK);
    S[i] = (j == k) ? 0.f : expf(S[i] - cm[b*KTOK + k]);
}

__global__ void fid_kernel(const float* __restrict__ g, const float* __restrict__ cm,
                           float* __restrict__ fid) {
    int i = blockIdx.x * blockDim.x + threadIdx.x;
    if (i >= BATCH*KTOK) return;
    fid[i] = expf(g[i] - cm[i]);
}

__global__ void colsum_kernel(const float* __restrict__ A, float* __restrict__ cs) {
    int i = blockIdx.x * blockDim.x + threadIdx.x;
    if (i >= BATCH*KTOK) return;
    int b = i / KTOK, k = i % KTOK;
    const float* Ab = A + (size_t)b*KTOK*KTOK + k;
    double s = 0.0;
    for (int j = 0; j < KTOK; j++) s += (double)Ab[(size_t)j*KTOK];
    cs[i] = (float)s;
}

__global__ void build_kernel(const float* __restrict__ A,
                             const float* __restrict__ fid,
                             const float* __restrict__ cs,
                             float* __restrict__ M, float* __restrict__ Inv) {
    size_t i = (size_t)blockIdx.x * blockDim.x + threadIdx.x;
    if (i >= (size_t)BATCH*KTOK*KTOK) return;
    int k = (int)(i % KTOK);
    size_t t = i / KTOK;
    int j = (int)(t % KTOK);
    int b = (int)(t / KTOK);
    float v;
    if (j == 0) v = fid[b*KTOK + k];
    else        v = -A[i] + (j == k ? cs[b*KTOK + k] : 0.f);
    M[i]   = v;
    Inv[i] = (j == k) ? 1.f : 0.f;
}

__global__ void copyw_kernel(const float* __restrict__ M, float* __restrict__ W, int k0) {
    int i = blockIdx.x * blockDim.x + threadIdx.x;
    if (i >= BATCH*KTOK*NB) return;
    int t = i % NB;
    int r = (i / NB) % KTOK;
    int b = i / (NB*KTOK);
    float w = M[(size_t)b*KTOK*KTOK + (size_t)r*KTOK + k0 + t];
    if (r == k0 + t) w -= 1.f;
    W[i] = w;
}

// in-smem fp64 Gauss-Jordan inversion of the 128x128 pivot block (fp32 in/out)
__global__ void pivot_inv_kernel(const float* __restrict__ M,
                                 float* __restrict__ Pinv, int k0) {
    extern __shared__ double P[];   // NB x (NB+1)
    int b = blockIdx.x;
    const float* Mb = M + (size_t)b*KTOK*KTOK;
    for (int i = threadIdx.x; i < NB*NB; i += blockDim.x) {
        int r = i >> 7, c = i & 127;
        P[r*129 + c] = (double)Mb[(size_t)(k0 + r)*KTOK + k0 + c];
    }
    __syncthreads();
    int r  = threadIdx.x >> 2;          // 512 threads -> 4 threads per row
    int c0 = (threadIdx.x & 3) * 32;
    for (int j = 0; j < NB; j++) {
        double pv   = P[j*129 + j];
        double pinv = 1.0 / pv;
        double f    = P[r*129 + j];
        __syncthreads();
        if (r == j) {
            for (int c = c0; c < c0 + 32; c++)
                P[j*129 + c] = (c == j) ? pinv : P[j*129 + c] * pinv;
        }
        __syncthreads();
        if (r != j) {
            for (int c = c0; c < c0 + 32; c++) {
                double nv = (c == j) ? (-f * pinv)
                                     : (P[r*129 + c] - f * P[j*129 + c]);
                P[r*129 + c] = nv;
            }
        }
        __syncthreads();
    }
    for (int i = threadIdx.x; i < NB*NB; i += blockDim.x) {
        int rr = i >> 7, cc = i & 127;
        Pinv[(size_t)b*NB*NB + i] = (float)P[rr*129 + cc];
    }
}

// edge marginals + transposed store of a_ki into output buffer
__global__ void marginals_kernel(const float* __restrict__ A,
                                 const float* __restrict__ Inv,
                                 float* __restrict__ aik,
                                 float* __restrict__ out_a) {
    __shared__ float tInv[32][33];
    __shared__ float tV[32][33];
    __shared__ float dk[32];
    int b  = blockIdx.z;
    int k0 = blockIdx.x * 32;
    int j0 = blockIdx.y * 32;
    const float* Ib = Inv + (size_t)b*KTOK*KTOK;
    const float* Ab = A   + (size_t)b*KTOK*KTOK;
    int tx = threadIdx.x, ty = threadIdx.y;
    #pragma unroll
    for (int s = 0; s < 4; s++) {
        int kk = ty + 8*s;
        tInv[kk][tx] = Ib[(size_t)(k0 + kk)*KTOK + j0 + tx];
    }
    if (ty == 0) dk[tx] = Ib[(size_t)(k0 + tx)*KTOK + k0 + tx];
    __syncthreads();
    #pragma unroll
    for (int s = 0; s < 4; s++) {
        int jj = ty + 8*s;
        int j = j0 + jj, k = k0 + tx;
        float a = Ab[(size_t)j*KTOK + k];
        float v = ((k != 0) ? a * dk[tx] : 0.f)
                - ((j != 0) ? a * tInv[tx][jj] : 0.f);
        aik[(size_t)b*KTOK*KTOK + (size_t)j*KTOK + k] = v;
        tV[jj][tx] = v;
    }
    __syncthreads();
    #pragma unroll
    for (int s = 0; s < 4; s++) {
        int kk = ty + 8*s;
        out_a[(size_t)b*KTOK*(KTOK+1) + (size_t)(k0 + kk)*(KTOK+1) + (j0 + tx) + 1]
            = tV[tx][kk];
    }
}

__global__ void d0_kernel(const float* __restrict__ fid,
                          const float* __restrict__ Inv,
                          float* __restrict__ out_a) {
    int i = blockIdx.x * blockDim.x + threadIdx.x;
    if (i >= BATCH*KTOK) return;
    int b = i / KTOK, k = i % KTOK;
    out_a[(size_t)b*KTOK*(KTOK+1) + (size_t)k*(KTOK+1)]
        = fid[i] * Inv[(size_t)b*KTOK*KTOK + (size_t)k*KTOK];
}

__global__ void rank1_kernel(const float* __restrict__ out_a,
                             const float* __restrict__ exparam,
                             float* __restrict__ si) {
    int i = blockIdx.x * blockDim.x + threadIdx.x;
    if (i >= BATCH*KTOK*SEM) return;
    int c  = i % SEM;
    int bj = i / SEM;
    int b = bj / KTOK, j = bj % KTOK;
    float a0 = out_a[(size_t)b*KTOK*(KTOK+1) + (size_t)j*(KTOK+1)];
    si[i] += a0 * exparam[c];
}

// ---------------- generic strided batched fp32 GEMM ----------------
#define FLAG_BIAS  1
#define FLAG_TANH  2

__global__ __launch_bounds__(256)
void gemm_kernel(const float* __restrict__ A, const float* __restrict__ B,
                 float* __restrict__ C, const float* __restrict__ bias,
                 int M, int N, int Kd,
                 long long sAb, int sAm, int sAk,
                 long long sBb, int sBk, int sBn,
                 long long sCb, int sCm,
                 float alpha, float beta, int flags) {
    __shared__ float As[16][68];
    __shared__ float Bs[16][68];
    int b = blockIdx.z;
    A += (size_t)b * sAb;
    B += (size_t)b * sBb;
    C += (size_t)b * sCb;
    int m0 = blockIdx.y * 64, n0 = blockIdx.x * 64;
    int tid = threadIdx.x;
    int tx = tid & 15, ty = tid >> 4;
    float acc[4][4] = {};
    for (int k0 = 0; k0 < Kd; k0 += 16) {
        if (sAk == 1) {                 // contiguous in K
            int kk = tid & 15, mm = tid >> 4;
            #pragma unroll
            for (int p = 0; p < 4; p++) {
                int m = mm + p*16;
                int gm = m0 + m, gk = k0 + kk;
                As[kk][m] = (gm < M && gk < Kd) ? A[(size_t)gm*sAm + gk] : 0.f;
            }
        } else {
            int mm = tid & 63, kk = tid >> 6;
            #pragma unroll
            for (int p = 0; p < 4; p++) {
                int k = kk + p*4;
                int gm = m0 + mm, gk = k0 + k;
                As[k][mm] = (gm < M && gk < Kd) ? A[(size_t)gm*sAm + (size_t)gk*sAk] : 0.f;
            }
        }
        if (sBn == 1) {
            int nn = tid & 63, kk = tid >> 6;
            #pragma unroll
            for (int p = 0; p < 4; p++) {
                int k = kk + p*4;
                int gn = n0 + nn, gk = k0 + k;
                Bs[k][nn] = (gn < N && gk < Kd) ? B[(size_t)gk*sBk + gn] : 0.f;
            }
        } else {
            int kk = tid & 15, nn = tid >> 4;
            #pragma unroll
            for (int p = 0; p < 4; p++) {
                int n = nn + p*16;
                int gn = n0 + n, gk = k0 + kk;
                Bs[kk][n] = (gn < N && gk < Kd) ? B[(size_t)gk*sBk + (size_t)gn*sBn] : 0.f;
            }
        }
        __syncthreads();
        #pragma unroll
        for (int kk = 0; kk < 16; kk++) {
            float4 a4 = *(const float4*)&As[kk][ty*4];
            float4 b4 = *(const float4*)&Bs[kk][tx*4];
            float a[4] = {a4.x, a4.y, a4.z, a4.w};
            float bb[4] = {b4.x, b4.y, b4.z, b4.w};
            #pragma unroll
            for (int i2 = 0; i2 < 4; i2++)
                #pragma unroll
                for (int j2 = 0; j2 < 4; j2++)
                    acc[i2][j2] += a[i2] * bb[j2];
        }
        __syncthreads();
    }
    #pragma unroll
    for (int i2 = 0; i2 < 4; i2++) {
        int gm = m0 + ty*4 + i2;
        if (gm >= M) continue;
        #pragma unroll
        for (int j2 = 0; j2 < 4; j2++) {
            int gn = n0 + tx*4 + j2;
            if (gn >= N) continue;
            size_t ci = (size_t)gm * sCm + gn;
            float v = alpha * acc[i2][j2];
            if (beta != 0.f)       v += beta * C[ci];
            if (flags & FLAG_BIAS) v += bias[gn];
            if (flags & FLAG_TANH) v = tanhf(v);
            C[ci] = v;
        }
    }
}

static inline void launch_gemm(const float* A, const float* B, float* C,
                               const float* bias,
                               int M, int N, int Kd,
                               long long sAb, int sAm, int sAk,
                               long long sBb, int sBk, int sBn,
                               long long sCb, int sCm,
                               float alpha, float beta, int flags, int batch) {
    dim3 g((N + 63) / 64, (M + 63) / 64, batch);
    gemm_kernel<<<g, 256>>>(A, B, C, bias, M, N, Kd,
                            sAb, sAm, sAk, sBb, sBk, sBn, sCb, sCm,
                            alpha, beta, flags);
}

// ---------------- driver ----------------
extern "C" void kernel_launch(void* const* d_in, const int* in_sizes, int n_in,
                              void* d_out, int out_size) {
    const float* x       = (const float*)d_in[0];
    const float* Wp_w    = (const float*)d_in[1];
    const float* Wp_b    = (const float*)d_in[2];
    const float* Wc_w    = (const float*)d_in[3];
    const float* Wc_b    = (const float*)d_in[4];
    const float* fi_w    = (const float*)d_in[5];
    const float* Wa_w    = (const float*)d_in[6];
    const float* exparam = (const float*)d_in[7];
    const float* Wr_w    = (const float*)d_in[8];
    const float* Wr_b    = (const float*)d_in[9];

    float* out_r = (float*)d_out;
    float* out_a = out_r + (size_t)BATCH*KTOK*SEM;

    float *ei, *di, *uj, *uk, *vv, *Am, *aik, *gg, *cm, *fid, *si, *ci;
    float *cs, *Mf, *If, *Wf, *Pvf, *RMf, *RIf;
    cudaGetSymbolAddress((void**)&ei,  g_ei);
    cudaGetSymbolAddress((void**)&di,  g_di);
    cudaGetSymbolAddress((void**)&uj,  g_uj);
    cudaGetSymbolAddress((void**)&uk,  g_uk);
    cudaGetSymbolAddress((void**)&vv,  g_v);
    cudaGetSymbolAddress((void**)&Am,  g_A);
    cudaGetSymbolAddress((void**)&aik, g_aik);
    cudaGetSymbolAddress((void**)&gg,  g_g);
    cudaGetSymbolAddress((void**)&cm,  g_cm);
    cudaGetSymbolAddress((void**)&fid, g_fid);
    cudaGetSymbolAddress((void**)&si,  g_si);
    cudaGetSymbolAddress((void**)&ci,  g_ci);
    cudaGetSymbolAddress((void**)&cs,  g_cs);
    cudaGetSymbolAddress((void**)&Mf,  g_Mf);
    cudaGetSymbolAddress((void**)&If,  g_If);
    cudaGetSymbolAddress((void**)&Wf,  g_Wf);
    cudaGetSymbolAddress((void**)&Pvf, g_Pvf);
    cudaGetSymbolAddress((void**)&RMf, g_RMf);
    cudaGetSymbolAddress((void**)&RIf, g_RIf);

    cudaFuncSetAttribute(pivot_inv_kernel,
                         cudaFuncAttributeMaxDynamicSharedMemorySize, NB*(NB+1)*8);

    // 1) semantic/structural split
    split_kernel<<<(BATCH*KTOK*SEM + 255)/256, 256>>>(x, ei, di);

    // 2) u_j = tanh(d W_p + b), u_k = tanh(d W_c + b)
    launch_gemm(di, Wp_w, uj, Wp_b, BATCH*KTOK, STRD, STRD,
                0, STRD, 1, 0, STRD, 1, 0, STRD, 1.f, 0.f, FLAG_BIAS|FLAG_TANH, 1);
    launch_gemm(di, Wc_w, uk, Wc_b, BATCH*KTOK, STRD, STRD,
                0, STRD, 1, 0, STRD, 1, 0, STRD, 1.f, 0.f, FLAG_BIAS|FLAG_TANH, 1);

    // 3) v = u_k @ Wa^T
    launch_gemm(uk, Wa_w, vv, nullptr, BATCH*KTOK, STRD, STRD,
                0, STRD, 1, 0, 1, STRD, 0, STRD, 1.f, 0.f, 0, 1);

    // 4) raw root scores g = d @ fi_w
    fi_kernel<<<(BATCH*KTOK + 7)/8, 256>>>(di, fi_w, gg);

    // 5) raw bilinear scores S = u_j v^T  (batched NT GEMM)
    launch_gemm(uj, vv, Am, nullptr, KTOK, KTOK, STRD,
                (long long)KTOK*STRD, STRD, 1,
                (long long)KTOK*STRD, 1, STRD,
                (long long)KTOK*KTOK, KTOK, 1.f, 0.f, 0, BATCH);

    // 6) per-column max normalization (tree marginals are column-scale invariant)
    colmax_kernel<<<(BATCH*KTOK + 255)/256, 256>>>(Am, gg, cm);
    normA_kernel<<<(unsigned)(((size_t)BATCH*KTOK*KTOK + 255)/256), 256>>>(Am, cm);
    fid_kernel<<<(BATCH*KTOK + 255)/256, 256>>>(gg, cm, fid);
    colsum_kernel<<<(BATCH*KTOK + 255)/256, 256>>>(Am, cs);

    // 7) Laplacian (fp32) + identity
    build_kernel<<<(unsigned)(((size_t)BATCH*KTOK*KTOK + 255)/256), 256>>>(Am, fid, cs, Mf, If);

    // 8) fp32 blocked Gauss-Jordan inversion: If = Mf^{-1}
    for (int s = 0; s < NSTEP; s++) {
        int k0 = s * NB;
        copyw_kernel<<<(BATCH*KTOK*NB + 255)/256, 256>>>(Mf, Wf, k0);
        pivot_inv_kernel<<<BATCH, 512, NB*(NB+1)*8>>>(Mf, Pvf, k0);
        // R_M = P^-1 @ M[pivot rows, k0:]
        launch_gemm(Pvf, Mf + (size_t)k0*KTOK + k0, RMf, nullptr, NB, KTOK - k0, NB,
                    (long long)NB*NB, NB, 1,
                    (long long)KTOK*KTOK, KTOK, 1,
                    (long long)NB*KTOK, KTOK, 1.f, 0.f, 0, BATCH);
        // R_I = P^-1 @ Inv[pivot rows, :k0+NB]
        launch_gemm(Pvf, If + (size_t)k0*KTOK, RIf, nullptr, NB, k0 + NB, NB,
                    (long long)NB*NB, NB, 1,
                    (long long)KTOK*KTOK, KTOK, 1,
                    (long long)NB*(KTOK+NB), KTOK+NB, 1.f, 0.f, 0, BATCH);
        // M[:, k0:] -= W @ R_M
        launch_gemm(Wf, RMf, Mf + k0, nullptr, KTOK, KTOK - k0, NB,
                    (long long)KTOK*NB, NB, 1,
                    (long long)NB*KTOK, KTOK, 1,
                    (long long)KTOK*KTOK, KTOK, -1.f, 1.f, 0, BATCH);
        // Inv[:, :k0+NB] -= W @ R_I
        launch_gemm(Wf, RIf, If, nullptr, KTOK, k0 + NB, NB,
                    (long long)KTOK*NB, NB, 1,
                    (long long)NB*(KTOK+NB), KTOK+NB, 1,
                    (long long)KTOK*KTOK, KTOK, -1.f, 1.f, 0, BATCH);
    }

    // 9) edge marginals a_ik, transposed a_ki into output, root column d0
    marginals_kernel<<<dim3(KTOK/32, KTOK/32, BATCH), dim3(32, 8)>>>(Am, If, aik, out_a);
    d0_kernel<<<(BATCH*KTOK + 255)/256, 256>>>(fid, If, out_a);

    // 10) si = a_ki[:,:,1:] @ e_i + a_ki[:,:,0] x exparam
    launch_gemm(out_a + 1, ei, si, nullptr, KTOK, SEM, KTOK,
                (long long)KTOK*(KTOK+1), KTOK+1, 1,
                (long long)KTOK*SEM, SEM, 1,
                (long long)KTOK*SEM, SEM, 1.f, 0.f, 0, BATCH);
    rank1_kernel<<<(BATCH*KTOK*SEM + 255)/256, 256>>>(out_a, exparam, si);

    // 11) ci = a_ik @ e_i
    launch_gemm(aik, ei, ci, nullptr, KTOK, SEM, KTOK,
                (long long)KTOK*KTOK, KTOK, 1,
                (long long)KTOK*SEM, SEM, 1,
                (long long)KTOK*SEM, SEM, 1.f, 0.f, 0, BATCH);

    // 12) r = tanh([e|si|ci] @ Wr + b)   as 3 accumulating GEMMs
    launch_gemm(ei, Wr_w, out_r, nullptr, BATCH*KTOK, SEM, STRD,
                0, SEM, 1, 0, SEM, 1, 0, SEM, 1.f, 0.f, 0, 1);
    launch_gemm(si, Wr_w + (size_t)384*384, out_r, nullptr, BATCH*KTOK, SEM, STRD,
                0, SEM, 1, 0, SEM, 1, 0, SEM, 1.f, 1.f, 0, 1);
    launch_gemm(ci, Wr_w + (size_t)768*384, out_r, Wr_b, BATCH*KTOK, SEM, STRD,
                0, SEM, 1, 0, SEM, 1, 0, SEM, 1.f, 1.f, FLAG_BIAS|FLAG_TANH, 1);
}

// round 6
// speedup vs baseline: 4.0214x; 1.0291x over previous
#include <cuda_runtime.h>
#include <math.h>
#include <stdint.h>

#define BATCH 16
#define KTOK  1024
#define DD    768
#define SEM   384
#define STRD  384
#define NB    128
#define NSTEP (KTOK/NB)

// ---------------- device scratch (bss, no runtime allocation) ----------------
__device__ float  g_ei [BATCH*KTOK*SEM];
__device__ float  g_di [BATCH*KTOK*STRD];
__device__ float  g_uj [BATCH*KTOK*STRD];
__device__ float  g_uk [BATCH*KTOK*STRD];
__device__ float  g_v  [BATCH*KTOK*STRD];
__device__ float  g_A  [(size_t)BATCH*KTOK*KTOK];   // raw scores, then normalized A
__device__ float  g_g  [BATCH*KTOK];                // raw root scores (pre-exp)
__device__ float  g_cm [BATCH*KTOK];                // per-column max
__device__ float  g_fid[BATCH*KTOK];                // normalized root weight exp(g-m)
__device__ float  g_cs [BATCH*KTOK];                // column sums
__device__ float  g_Mf [(size_t)BATCH*KTOK*KTOK];
__device__ float  g_If [(size_t)BATCH*KTOK*KTOK];
__device__ float  g_Wf [BATCH*KTOK*NB];
__device__ float  g_Pvf[BATCH*NB*NB];
__device__ float  g_RMf[BATCH*NB*KTOK];
__device__ float  g_RIf[BATCH*NB*(KTOK+NB)];
__device__ float  g_si [BATCH*KTOK*SEM];
__device__ float  g_ci [BATCH*KTOK*SEM];

// ---------------- elementwise kernels ----------------
__global__ void split_kernel(const float* __restrict__ x,
                             float* __restrict__ ei, float* __restrict__ di) {
    int i = blockIdx.x * blockDim.x + threadIdx.x;
    if (i >= BATCH*KTOK*SEM) return;
    int c  = i % SEM;
    int bk = i / SEM;
    const float* xr = x + (size_t)bk * DD;
    ei[i] = xr[c < 192 ? c       : c + 192];
    di[i] = xr[c < 192 ? c + 192 : c + 384];
}

// raw root score g = d @ fi_w
__global__ void fi_kernel(const float* __restrict__ di,
                          const float* __restrict__ fw,
                          float* __restrict__ g) {
    int row  = blockIdx.x * 8 + (threadIdx.x >> 5);
    int lane = threadIdx.x & 31;
    if (row >= BATCH*KTOK) return;
    const float* d = di + (size_t)row * STRD;
    float s = 0.f;
    for (int c = lane; c < STRD; c += 32) s += d[c] * fw[c];
    #pragma unroll
    for (int o = 16; o; o >>= 1) s += __shfl_xor_sync(0xffffffffu, s, o);
    if (lane == 0) g[row] = s;
}

// m_k = max(g_k, max_{j!=k} S[j,k]); fid = exp(g - m)
__global__ void colmax_fid_kernel(const float* __restrict__ S,
                                  const float* __restrict__ g,
                                  float* __restrict__ cm,
                                  float* __restrict__ fid) {
    int i = blockIdx.x * blockDim.x + threadIdx.x;
    if (i >= BATCH*KTOK) return;
    int b = i / KTOK, k = i % KTOK;
    const float* Sb = S + (size_t)b*KTOK*KTOK + k;
    float m = g[i];
    for (int j = 0; j < KTOK; j++) {
        if (j == k) continue;
        m = fmaxf(m, Sb[(size_t)j*KTOK]);
    }
    cm[i]  = m;
    fid[i] = expf(g[i] - m);
}

// A[j,k] = (j==k) ? 0 : exp(S - m_k)  (in place over S)
__global__ void normA_kernel(float* __restrict__ S, const float* __restrict__ cm) {
    size_t i = (size_t)blockIdx.x * blockDim.x + threadIdx.x;
    if (i >= (size_t)BATCH*KTOK*KTOK) return;
    int k = (int)(i % KTOK);
    size_t t = i / KTOK;
    int j = (int)(t % KTOK);
    int b = (int)(t / KTOK);
    S[i] = (j == k) ? 0.f : expf(S[i] - cm[b*KTOK + k]);
}

__global__ void colsum_kernel(const float* __restrict__ A, float* __restrict__ cs) {
    int i = blockIdx.x * blockDim.x + threadIdx.x;
    if (i >= BATCH*KTOK) return;
    int b = i / KTOK, k = i % KTOK;
    const float* Ab = A + (size_t)b*KTOK*KTOK + k;
    double s = 0.0;
    for (int j = 0; j < KTOK; j++) s += (double)Ab[(size_t)j*KTOK];
    cs[i] = (float)s;
}

__global__ void build_kernel(const float* __restrict__ A,
                             const float* __restrict__ fid,
                             const float* __restrict__ cs,
                             float* __restrict__ M, float* __restrict__ Inv) {
    size_t i = (size_t)blockIdx.x * blockDim.x + threadIdx.x;
    if (i >= (size_t)BATCH*KTOK*KTOK) return;
    int k = (int)(i % KTOK);
    size_t t = i / KTOK;
    int j = (int)(t % KTOK);
    int b = (int)(t / KTOK);
    float v;
    if (j == 0) v = fid[b*KTOK + k];
    else        v = -A[i] + (j == k ? cs[b*KTOK + k] : 0.f);
    M[i]   = v;
    Inv[i] = (j == k) ? 1.f : 0.f;
}

__global__ void copyw_kernel(const float* __restrict__ M, float* __restrict__ W, int k0) {
    int i = blockIdx.x * blockDim.x + threadIdx.x;
    if (i >= BATCH*KTOK*NB) return;
    int t = i % NB;
    int r = (i / NB) % KTOK;
    int b = i / (NB*KTOK);
    float w = M[(size_t)b*KTOK*KTOK + (size_t)r*KTOK + k0 + t];
    if (r == k0 + t) w -= 1.f;
    W[i] = w;
}

// in-smem fp64 Gauss-Jordan inversion of the 128x128 pivot block (fp32 in/out)
__global__ void pivot_inv_kernel(const float* __restrict__ M,
                                 float* __restrict__ Pinv, int k0) {
    extern __shared__ double P[];           // NB x (NB+1), then rowbuf[NB]
    double* rowbuf = P + NB*(NB+1);
    int b = blockIdx.x;
    int tid = threadIdx.x;
    const float* Mb = M + (size_t)b*KTOK*KTOK;
    for (int i = tid; i < NB*NB; i += blockDim.x) {
        int r = i >> 7, c = i & 127;
        P[r*129 + c] = (double)Mb[(size_t)(k0 + r)*KTOK + k0 + c];
    }
    __syncthreads();
    int r  = tid >> 2;                      // 512 threads -> 4 threads per row
    int c0 = (tid & 3) * 32;
    for (int j = 0; j < NB; j++) {
        double pinv = 1.0 / P[j*129 + j];
        double f    = P[r*129 + j];
        if (tid < NB) rowbuf[tid] = (tid == j) ? pinv : P[j*129 + tid] * pinv;
        __syncthreads();
        if (r == j) {
            for (int c = c0; c < c0 + 32; c++) P[j*129 + c] = rowbuf[c];
        } else {
            for (int c = c0; c < c0 + 32; c++) {
                P[r*129 + c] = (c == j) ? (-f * pinv)
                                        : fma(-f, rowbuf[c], P[r*129 + c]);
            }
        }
        __syncthreads();
    }
    for (int i = tid; i < NB*NB; i += blockDim.x) {
        int rr = i >> 7, cc = i & 127;
        Pinv[(size_t)b*NB*NB + i] = (float)P[rr*129 + cc];
    }
}

// edge marginals -> transposed store of a_ki into output buffer (no aik array)
__global__ void marginals_kernel(const float* __restrict__ A,
                                 const float* __restrict__ Inv,
                                 float* __restrict__ out_a) {
    __shared__ float tInv[32][33];
    __shared__ float tV[32][33];
    __shared__ float dk[32];
    int b  = blockIdx.z;
    int k0 = blockIdx.x * 32;
    int j0 = blockIdx.y * 32;
    const float* Ib = Inv + (size_t)b*KTOK*KTOK;
    const float* Ab = A   + (size_t)b*KTOK*KTOK;
    int tx = threadIdx.x, ty = threadIdx.y;
    #pragma unroll
    for (int s = 0; s < 4; s++) {
        int kk = ty + 8*s;
        tInv[kk][tx] = Ib[(size_t)(k0 + kk)*KTOK + j0 + tx];
    }
    if (ty == 0) dk[tx] = Ib[(size_t)(k0 + tx)*KTOK + k0 + tx];
    __syncthreads();
    #pragma unroll
    for (int s = 0; s < 4; s++) {
        int jj = ty + 8*s;
        int j = j0 + jj, k = k0 + tx;
        float a = Ab[(size_t)j*KTOK + k];
        float v = ((k != 0) ? a * dk[tx] : 0.f)
                - ((j != 0) ? a * tInv[tx][jj] : 0.f);
        tV[jj][tx] = v;
    }
    __syncthreads();
    #pragma unroll
    for (int s = 0; s < 4; s++) {
        int kk = ty + 8*s;
        out_a[(size_t)b*KTOK*(KTOK+1) + (size_t)(k0 + kk)*(KTOK+1) + (j0 + tx) + 1]
            = tV[tx][kk];
    }
}

__global__ void d0_kernel(const float* __restrict__ fid,
                          const float* __restrict__ Inv,
                          float* __restrict__ out_a) {
    int i = blockIdx.x * blockDim.x + threadIdx.x;
    if (i >= BATCH*KTOK) return;
    int b = i / KTOK, k = i % KTOK;
    out_a[(size_t)b*KTOK*(KTOK+1) + (size_t)k*(KTOK+1)]
        = fid[i] * Inv[(size_t)b*KTOK*KTOK + (size_t)k*KTOK];
}

__global__ void rank1_kernel(const float* __restrict__ out_a,
                             const float* __restrict__ exparam,
                             float* __restrict__ si) {
    int i = blockIdx.x * blockDim.x + threadIdx.x;
    if (i >= BATCH*KTOK*SEM) return;
    int c  = i % SEM;
    int bj = i / SEM;
    int b = bj / KTOK, j = bj % KTOK;
    float a0 = out_a[(size_t)b*KTOK*(KTOK+1) + (size_t)j*(KTOK+1)];
    si[i] += a0 * exparam[c];
}

// ---------------- 128x128x16 double-buffered fp32 GEMM ----------------
// Requires: M % 128 == 0, N % 128 == 0, K % 16 == 0 (true for all call sites).
#define FLAG_BIAS  1
#define FLAG_TANH  2

__global__ __launch_bounds__(256)
void gemm_kernel(const float* __restrict__ A, const float* __restrict__ B,
                 float* __restrict__ C, const float* __restrict__ bias,
                 int M, int N, int Kd,
                 long long sAb, int sAm, int sAk,
                 long long sBb, int sBk, int sBn,
                 long long sCb, int sCm,
                 float alpha, float beta, int flags) {
    __shared__ float As[2][16][132];
    __shared__ float Bs[2][16][132];
    int bz = blockIdx.z;
    A += (size_t)bz * sAb;
    B += (size_t)bz * sBb;
    C += (size_t)bz * sCb;
    int m0 = blockIdx.y * 128, n0 = blockIdx.x * 128;
    int tid = threadIdx.x;
    int tx = tid & 15, ty = tid >> 4;

    const bool aK = (sAk == 1);   // A contiguous in K
    const bool bN = (sBn == 1);   // B contiguous in N
    const float* ap;
    const float* bp;
    int a_r, a_c, b_r, b_c;
    if (aK) { int am = tid >> 1, k8 = (tid & 1) * 8;
              ap = A + (size_t)(m0 + am) * sAm + k8; a_r = k8; a_c = am; }
    else    { int ak = tid >> 4, m8 = (tid & 15) * 8;
              ap = A + (size_t)(m0 + m8) * sAm + (size_t)ak * sAk; a_r = ak; a_c = m8; }
    if (bN) { int bk = tid >> 4, n8 = (tid & 15) * 8;
              bp = B + (size_t)bk * sBk + (n0 + n8); b_r = bk; b_c = n8; }
    else    { int bn = tid >> 1, k8 = (tid & 1) * 8;
              bp = B + (size_t)(n0 + bn) * sBn + (size_t)k8 * sBk; b_r = k8; b_c = bn; }

    float ra[8], rb[8];
    float acc[8][8];
    #pragma unroll
    for (int i = 0; i < 8; i++)
        #pragma unroll
        for (int j = 0; j < 8; j++) acc[i][j] = 0.f;

    int nk = Kd >> 4;

    // ---- prologue: load block 0, stage into buffer 0 ----
    if (aK) {
        #pragma unroll
        for (int i = 0; i < 8; i++) ra[i] = ap[i];
        ap += 16;
    } else {
        #pragma unroll
        for (int i = 0; i < 8; i++) ra[i] = ap[(size_t)i * sAm];
        ap += (size_t)16 * sAk;
    }
    if (bN) {
        #pragma unroll
        for (int i = 0; i < 8; i++) rb[i] = bp[i];
        bp += (size_t)16 * sBk;
    } else {
        #pragma unroll
        for (int i = 0; i < 8; i++) rb[i] = bp[(size_t)i * sBk];
        bp += (size_t)16 * sBk;
    }
    if (aK) {
        #pragma unroll
        for (int i = 0; i < 8; i++) As[0][a_r + i][a_c] = ra[i];
    } else {
        #pragma unroll
        for (int i = 0; i < 8; i++) As[0][a_r][a_c + i] = ra[i];
    }
    if (bN) {
        #pragma unroll
        for (int i = 0; i < 8; i++) Bs[0][b_r][b_c + i] = rb[i];
    } else {
        #pragma unroll
        for (int i = 0; i < 8; i++) Bs[0][b_r + i][b_c] = rb[i];
    }
    __syncthreads();

    for (int kt = 0; kt < nk; kt++) {
        int cur = kt & 1;
        if (kt + 1 < nk) {
            if (aK) {
                #pragma unroll
                for (int i = 0; i < 8; i++) ra[i] = ap[i];
                ap += 16;
            } else {
                #pragma unroll
                for (int i = 0; i < 8; i++) ra[i] = ap[(size_t)i * sAm];
                ap += (size_t)16 * sAk;
            }
            if (bN) {
                #pragma unroll
                for (int i = 0; i < 8; i++) rb[i] = bp[i];
                bp += (size_t)16 * sBk;
            } else {
                #pragma unroll
                for (int i = 0; i < 8; i++) rb[i] = bp[(size_t)i * sBk];
                bp += (size_t)16 * sBk;
            }
        }
        #pragma unroll
        for (int kk = 0; kk < 16; kk++) {
            float4 a0 = *(const float4*)&As[cur][kk][ty*8];
            float4 a1 = *(const float4*)&As[cur][kk][ty*8 + 4];
            float4 b0 = *(const float4*)&Bs[cur][kk][tx*8];
            float4 b1 = *(const float4*)&Bs[cur][kk][tx*8 + 4];
            float av[8] = {a0.x, a0.y, a0.z, a0.w, a1.x, a1.y, a1.z, a1.w};
            float bv[8] = {b0.x, b0.y, b0.z, b0.w, b1.x, b1.y, b1.z, b1.w};
            #pragma unroll
            for (int i = 0; i < 8; i++)
                #pragma unroll
                for (int j = 0; j < 8; j++)
                    acc[i][j] += av[i] * bv[j];
        }
        if (kt + 1 < nk) {
            int nxt = cur ^ 1;
            if (aK) {
                #pragma unroll
                for (int i = 0; i < 8; i++) As[nxt][a_r + i][a_c] = ra[i];
            } else {
                #pragma unroll
                for (int i = 0; i < 8; i++) As[nxt][a_r][a_c + i] = ra[i];
            }
            if (bN) {
                #pragma unroll
                for (int i = 0; i < 8; i++) Bs[nxt][b_r][b_c + i] = rb[i];
            } else {
                #pragma unroll
                for (int i = 0; i < 8; i++) Bs[nxt][b_r + i][b_c] = rb[i];
            }
        }
        __syncthreads();
    }

    // ---- epilogue ----
    #pragma unroll
    for (int i = 0; i < 8; i++) {
        float* cp = C + (size_t)(m0 + ty*8 + i) * sCm + n0 + tx*8;
        #pragma unroll
        for (int g = 0; g < 2; g++) {
            float v0 = alpha * acc[i][4*g + 0];
            float v1 = alpha * acc[i][4*g + 1];
            float v2 = alpha * acc[i][4*g + 2];
            float v3 = alpha * acc[i][4*g + 3];
            if (beta != 0.f) {
                float4 o = *(const float4*)(cp + 4*g);
                v0 += beta * o.x; v1 += beta * o.y;
                v2 += beta * o.z; v3 += beta * o.w;
            }
            if (flags & FLAG_BIAS) {
                const float* bb = bias + n0 + tx*8 + 4*g;
                v0 += bb[0]; v1 += bb[1]; v2 += bb[2]; v3 += bb[3];
            }
            if (flags & FLAG_TANH) {
                v0 = tanhf(v0); v1 = tanhf(v1);
                v2 = tanhf(v2); v3 = tanhf(v3);
            }
            float4 w; w.x = v0; w.y = v1; w.z = v2; w.w = v3;
            *(float4*)(cp + 4*g) = w;
        }
    }
}

static inline void launch_gemm(const float* A, const float* B, float* C,
                               const float* bias,
                               int M, int N, int Kd,
                               long long sAb, int sAm, int sAk,
                               long long sBb, int sBk, int sBn,
                               long long sCb, int sCm,
                               float alpha, float beta, int flags, int batch) {
    dim3 g(N / 128, M / 128, batch);
    gemm_kernel<<<g, 256>>>(A, B, C, bias, M, N, Kd,
                            sAb, sAm, sAk, sBb, sBk, sBn, sCb, sCm,
                            alpha, beta, flags);
}

// ---------------- driver ----------------
extern "C" void kernel_launch(void* const* d_in, const int* in_sizes, int n_in,
                              void* d_out, int out_size) {
    const float* x       = (const float*)d_in[0];
    const float* Wp_w    = (const float*)d_in[1];
    const float* Wp_b    = (const float*)d_in[2];
    const float* Wc_w    = (const float*)d_in[3];
    const float* Wc_b    = (const float*)d_in[4];
    const float* fi_w    = (const float*)d_in[5];
    const float* Wa_w    = (const float*)d_in[6];
    const float* exparam = (const float*)d_in[7];
    const float* Wr_w    = (const float*)d_in[8];
    const float* Wr_b    = (const float*)d_in[9];

    float* out_r = (float*)d_out;
    float* out_a = out_r + (size_t)BATCH*KTOK*SEM;

    float *ei, *di, *uj, *uk, *vv, *Am, *gg, *cm, *fid, *si, *ci;
    float *cs, *Mf, *If, *Wf, *Pvf, *RMf, *RIf;
    cudaGetSymbolAddress((void**)&ei,  g_ei);
    cudaGetSymbolAddress((void**)&di,  g_di);
    cudaGetSymbolAddress((void**)&uj,  g_uj);
    cudaGetSymbolAddress((void**)&uk,  g_uk);
    cudaGetSymbolAddress((void**)&vv,  g_v);
    cudaGetSymbolAddress((void**)&Am,  g_A);
    cudaGetSymbolAddress((void**)&gg,  g_g);
    cudaGetSymbolAddress((void**)&cm,  g_cm);
    cudaGetSymbolAddress((void**)&fid, g_fid);
    cudaGetSymbolAddress((void**)&si,  g_si);
    cudaGetSymbolAddress((void**)&ci,  g_ci);
    cudaGetSymbolAddress((void**)&cs,  g_cs);
    cudaGetSymbolAddress((void**)&Mf,  g_Mf);
    cudaGetSymbolAddress((void**)&If,  g_If);
    cudaGetSymbolAddress((void**)&Wf,  g_Wf);
    cudaGetSymbolAddress((void**)&Pvf, g_Pvf);
    cudaGetSymbolAddress((void**)&RMf, g_RMf);
    cudaGetSymbolAddress((void**)&RIf, g_RIf);

    cudaFuncSetAttribute(pivot_inv_kernel,
                         cudaFuncAttributeMaxDynamicSharedMemorySize,
                         (NB*(NB+1) + NB) * 8);

    // 1) semantic/structural split
    split_kernel<<<(BATCH*KTOK*SEM + 255)/256, 256>>>(x, ei, di);

    // 2) u_j = tanh(d W_p + b), u_k = tanh(d W_c + b)
    launch_gemm(di, Wp_w, uj, Wp_b, BATCH*KTOK, STRD, STRD,
                0, STRD, 1, 0, STRD, 1, 0, STRD, 1.f, 0.f, FLAG_BIAS|FLAG_TANH, 1);
    launch_gemm(di, Wc_w, uk, Wc_b, BATCH*KTOK, STRD, STRD,
                0, STRD, 1, 0, STRD, 1, 0, STRD, 1.f, 0.f, FLAG_BIAS|FLAG_TANH, 1);

    // 3) v = u_k @ Wa^T
    launch_gemm(uk, Wa_w, vv, nullptr, BATCH*KTOK, STRD, STRD,
                0, STRD, 1, 0, 1, STRD, 0, STRD, 1.f, 0.f, 0, 1);

    // 4) raw root scores g = d @ fi_w
    fi_kernel<<<(BATCH*KTOK + 7)/8, 256>>>(di, fi_w, gg);

    // 5) raw bilinear scores S = u_j v^T  (batched NT GEMM)
    launch_gemm(uj, vv, Am, nullptr, KTOK, KTOK, STRD,
                (long long)KTOK*STRD, STRD, 1,
                (long long)KTOK*STRD, 1, STRD,
                (long long)KTOK*KTOK, KTOK, 1.f, 0.f, 0, BATCH);

    // 6) per-column max normalization (tree marginals are column-scale invariant)
    colmax_fid_kernel<<<(BATCH*KTOK + 255)/256, 256>>>(Am, gg, cm, fid);
    normA_kernel<<<(unsigned)(((size_t)BATCH*KTOK*KTOK + 255)/256), 256>>>(Am, cm);
    colsum_kernel<<<(BATCH*KTOK + 255)/256, 256>>>(Am, cs);

    // 7) Laplacian (fp32) + identity
    build_kernel<<<(unsigned)(((size_t)BATCH*KTOK*KTOK + 255)/256), 256>>>(Am, fid, cs, Mf, If);

    // 8) fp32 blocked Gauss-Jordan inversion: If = Mf^{-1} (fp64 pivot blocks)
    for (int s = 0; s < NSTEP; s++) {
        int k0 = s * NB;
        int nr = KTOK - k0 - NB;   // trailing columns of M still needed
        copyw_kernel<<<(BATCH*KTOK*NB + 255)/256, 256>>>(Mf, Wf, k0);
        pivot_inv_kernel<<<BATCH, 512, (NB*(NB+1) + NB) * 8>>>(Mf, Pvf, k0);
        if (nr > 0) {
            // R_M = P^-1 @ M[pivot rows, k0+NB:]
            launch_gemm(Pvf, Mf + (size_t)k0*KTOK + k0 + NB, RMf, nullptr, NB, nr, NB,
                        (long long)NB*NB, NB, 1,
                        (long long)KTOK*KTOK, KTOK, 1,
                        (long long)NB*KTOK, KTOK, 1.f, 0.f, 0, BATCH);
        }
        // R_I = P^-1 @ Inv[pivot rows, :k0+NB]
        launch_gemm(Pvf, If + (size_t)k0*KTOK, RIf, nullptr, NB, k0 + NB, NB,
                    (long long)NB*NB, NB, 1,
                    (long long)KTOK*KTOK, KTOK, 1,
                    (long long)NB*(KTOK+NB), KTOK+NB, 1.f, 0.f, 0, BATCH);
        if (nr > 0) {
            // M[:, k0+NB:] -= W @ R_M
            launch_gemm(Wf, RMf, Mf + k0 + NB, nullptr, KTOK, nr, NB,
                        (long long)KTOK*NB, NB, 1,
                        (long long)NB*KTOK, KTOK, 1,
                        (long long)KTOK*KTOK, KTOK, -1.f, 1.f, 0, BATCH);
        }
        // Inv[:, :k0+NB] -= W @ R_I
        launch_gemm(Wf, RIf, If, nullptr, KTOK, k0 + NB, NB,
                    (long long)KTOK*NB, NB, 1,
                    (long long)NB*(KTOK+NB), KTOK+NB, 1,
                    (long long)KTOK*KTOK, KTOK, -1.f, 1.f, 0, BATCH);
    }

    // 9) edge marginals -> out_a (transposed), root column d0
    marginals_kernel<<<dim3(KTOK/32, KTOK/32, BATCH), dim3(32, 8)>>>(Am, If, out_a);
    d0_kernel<<<(BATCH*KTOK + 255)/256, 256>>>(fid, If, out_a);

    // 10) si = a_ki[:,:,1:] @ e_i + a_ki[:,:,0] x exparam
    launch_gemm(out_a + 1, ei, si, nullptr, KTOK, SEM, KTOK,
                (long long)KTOK*(KTOK+1), KTOK+1, 1,
                (long long)KTOK*SEM, SEM, 1,
                (long long)KTOK*SEM, SEM, 1.f, 0.f, 0, BATCH);
    rank1_kernel<<<(BATCH*KTOK*SEM + 255)/256, 256>>>(out_a, exparam, si);

    // 11) ci = a_ik @ e_i, reading a_ik as the transpose of out_a[:,:,1:]
    launch_gemm(out_a + 1, ei, ci, nullptr, KTOK, SEM, KTOK,
                (long long)KTOK*(KTOK+1), 1, KTOK+1,
                (long long)KTOK*SEM, SEM, 1,
                (long long)KTOK*SEM, SEM, 1.f, 0.f, 0, BATCH);

    // 12) r = tanh([e|si|ci] @ Wr + b)   as 3 accumulating GEMMs
    launch_gemm(ei, Wr_w, out_r, nullptr, BATCH*KTOK, SEM, STRD,
                0, SEM, 1, 0, SEM, 1, 0, SEM, 1.f, 0.f, 0, 1);
    launch_gemm(si, Wr_w + (size_t)384*384, out_r, nullptr, BATCH*KTOK, SEM, STRD,
                0, SEM, 1, 0, SEM, 1, 0, SEM, 1.f, 1.f, 0, 1);
    launch_gemm(ci, Wr_w + (size_t)768*384, out_r, Wr_b, BATCH*KTOK, SEM, STRD,
                0, SEM, 1, 0, SEM, 1, 0, SEM, 1.f, 1.f, FLAG_BIAS|FLAG_TANH, 1);
}

// round 7
// speedup vs baseline: 4.3963x; 1.0932x over previous
#include <cuda_runtime.h>
#include <math.h>
#include <stdint.h>

#define BATCH 16
#define KTOK  1024
#define DD    768
#define SEM   384
#define STRD  384
#define NB    128
#define NSTEP (KTOK/NB)

// ---------------- device scratch (bss, no runtime allocation) ----------------
__device__ float  g_ei [BATCH*KTOK*SEM];
__device__ float  g_di [BATCH*KTOK*STRD];
__device__ float  g_uj [BATCH*KTOK*STRD];
__device__ float  g_uk [BATCH*KTOK*STRD];
__device__ float  g_v  [BATCH*KTOK*STRD];
__device__ float  g_A  [(size_t)BATCH*KTOK*KTOK];   // raw scores, then normalized A
__device__ float  g_g  [BATCH*KTOK];                // raw root scores (pre-exp)
__device__ float  g_cm [BATCH*KTOK];                // per-column max
__device__ float  g_fid[BATCH*KTOK];                // normalized root weight exp(g-m)
__device__ float  g_cs [BATCH*KTOK];                // column sums
__device__ float  g_G  [(size_t)BATCH*KTOK*KTOK];   // Laplacian -> in-place inverse
__device__ float  g_Wf [BATCH*KTOK*NB];
__device__ float  g_Pvf[BATCH*NB*NB];
__device__ float  g_Rf [BATCH*NB*KTOK];
__device__ float  g_si [BATCH*KTOK*SEM];
__device__ float  g_ci [BATCH*KTOK*SEM];

// ---------------- cp.async helpers ----------------
__device__ __forceinline__ uint32_t smem_u32(const void* p) {
    return (uint32_t)__cvta_generic_to_shared(p);
}
__device__ __forceinline__ void cp_async4(uint32_t s, const float* g) {
    asm volatile("cp.async.ca.shared.global [%0], [%1], 4;" :: "r"(s), "l"(g));
}
__device__ __forceinline__ void cp_async16(uint32_t s, const float* g) {
    asm volatile("cp.async.cg.shared.global [%0], [%1], 16;" :: "r"(s), "l"(g));
}
__device__ __forceinline__ void cp_commit() {
    asm volatile("cp.async.commit_group;");
}
template<int N> __device__ __forceinline__ void cp_wait() {
    asm volatile("cp.async.wait_group %0;" :: "n"(N));
}

// ---------------- elementwise kernels ----------------
__global__ void split_kernel(const float* __restrict__ x,
                             float* __restrict__ ei, float* __restrict__ di) {
    int i = blockIdx.x * blockDim.x + threadIdx.x;
    if (i >= BATCH*KTOK*SEM) return;
    int c  = i % SEM;
    int bk = i / SEM;
    const float* xr = x + (size_t)bk * DD;
    ei[i] = xr[c < 192 ? c       : c + 192];
    di[i] = xr[c < 192 ? c + 192 : c + 384];
}

__global__ void fi_kernel(const float* __restrict__ di,
                          const float* __restrict__ fw,
                          float* __restrict__ g) {
    int row  = blockIdx.x * 8 + (threadIdx.x >> 5);
    int lane = threadIdx.x & 31;
    if (row >= BATCH*KTOK) return;
    const float* d = di + (size_t)row * STRD;
    float s = 0.f;
    for (int c = lane; c < STRD; c += 32) s += d[c] * fw[c];
    #pragma unroll
    for (int o = 16; o; o >>= 1) s += __shfl_xor_sync(0xffffffffu, s, o);
    if (lane == 0) g[row] = s;
}

// m_k = max(g_k, max_{j!=k} S[j,k]); fid = exp(g - m)
__global__ void colmax_fid_kernel(const float* __restrict__ S,
                                  const float* __restrict__ g,
                                  float* __restrict__ cm,
                                  float* __restrict__ fid) {
    int i = blockIdx.x * blockDim.x + threadIdx.x;
    if (i >= BATCH*KTOK) return;
    int b = i / KTOK, k = i % KTOK;
    const float* Sb = S + (size_t)b*KTOK*KTOK + k;
    float m = g[i];
    for (int j = 0; j < KTOK; j++) {
        if (j == k) continue;
        m = fmaxf(m, Sb[(size_t)j*KTOK]);
    }
    cm[i]  = m;
    fid[i] = expf(g[i] - m);
}

// A[j,k] = (j==k) ? 0 : exp(S - m_k)  (in place over S)
__global__ void normA_kernel(float* __restrict__ S, const float* __restrict__ cm) {
    size_t i = (size_t)blockIdx.x * blockDim.x + threadIdx.x;
    if (i >= (size_t)BATCH*KTOK*KTOK) return;
    int k = (int)(i % KTOK);
    size_t t = i / KTOK;
    int j = (int)(t % KTOK);
    int b = (int)(t / KTOK);
    S[i] = (j == k) ? 0.f : expf(S[i] - cm[b*KTOK + k]);
}

__global__ void colsum_kernel(const float* __restrict__ A, float* __restrict__ cs) {
    int i = blockIdx.x * blockDim.x + threadIdx.x;
    if (i >= BATCH*KTOK) return;
    int b = i / KTOK, k = i % KTOK;
    const float* Ab = A + (size_t)b*KTOK*KTOK + k;
    double s = 0.0;
    for (int j = 0; j < KTOK; j++) s += (double)Ab[(size_t)j*KTOK];
    cs[i] = (float)s;
}

__global__ void build_kernel(const float* __restrict__ A,
                             const float* __restrict__ fid,
                             const float* __restrict__ cs,
                             float* __restrict__ G) {
    size_t i = (size_t)blockIdx.x * blockDim.x + threadIdx.x;
    if (i >= (size_t)BATCH*KTOK*KTOK) return;
    int k = (int)(i % KTOK);
    size_t t = i / KTOK;
    int j = (int)(t % KTOK);
    int b = (int)(t / KTOK);
    float v;
    if (j == 0) v = fid[b*KTOK + k];
    else        v = -A[i] + (j == k ? cs[b*KTOK + k] : 0.f);
    G[i] = v;
}

// W = G[:, J] - E_J  and  G[:, J] := E_J   (in-place GJ column extraction)
__global__ void copyw_kernel(float* __restrict__ G, float* __restrict__ W, int k0) {
    int i = blockIdx.x * blockDim.x + threadIdx.x;
    if (i >= BATCH*KTOK*NB) return;
    int t = i % NB;
    int r = (i / NB) % KTOK;
    int b = i / (NB*KTOK);
    size_t gi = (size_t)b*KTOK*KTOK + (size_t)r*KTOK + k0 + t;
    float w = G[gi];
    bool dg = (r == k0 + t);
    W[i]  = dg ? w - 1.f : w;
    G[gi] = dg ? 1.f : 0.f;
}

// in-smem fp64 Gauss-Jordan inversion of the 128x128 pivot block (fp32 in/out)
__global__ void pivot_inv_kernel(const float* __restrict__ G,
                                 float* __restrict__ Pinv, int k0) {
    extern __shared__ double P[];           // NB x (NB+1), then rowbuf[NB]
    double* rowbuf = P + NB*(NB+1);
    int b = blockIdx.x;
    int tid = threadIdx.x;
    const float* Gb = G + (size_t)b*KTOK*KTOK;
    for (int i = tid; i < NB*NB; i += blockDim.x) {
        int r = i >> 7, c = i & 127;
        P[r*129 + c] = (double)Gb[(size_t)(k0 + r)*KTOK + k0 + c];
    }
    __syncthreads();
    int r  = tid >> 2;                      // 512 threads -> 4 threads per row
    int c0 = (tid & 3) * 32;
    for (int j = 0; j < NB; j++) {
        double pinv = 1.0 / P[j*129 + j];
        double f    = P[r*129 + j];
        if (tid < NB) rowbuf[tid] = (tid == j) ? pinv : P[j*129 + tid] * pinv;
        __syncthreads();
        if (r == j) {
            for (int c = c0; c < c0 + 32; c++) P[j*129 + c] = rowbuf[c];
        } else {
            for (int c = c0; c < c0 + 32; c++) {
                P[r*129 + c] = (c == j) ? (-f * pinv)
                                        : fma(-f, rowbuf[c], P[r*129 + c]);
            }
        }
        __syncthreads();
    }
    for (int i = tid; i < NB*NB; i += blockDim.x) {
        int rr = i >> 7, cc = i & 127;
        Pinv[(size_t)b*NB*NB + i] = (float)P[rr*129 + cc];
    }
}

// edge marginals -> transposed store of a_ki into output buffer
__global__ void marginals_kernel(const float* __restrict__ A,
                                 const float* __restrict__ Inv,
                                 float* __restrict__ out_a) {
    __shared__ float tInv[32][33];
    __shared__ float tV[32][33];
    __shared__ float dk[32];
    int b  = blockIdx.z;
    int k0 = blockIdx.x * 32;
    int j0 = blockIdx.y * 32;
    const float* Ib = Inv + (size_t)b*KTOK*KTOK;
    const float* Ab = A   + (size_t)b*KTOK*KTOK;
    int tx = threadIdx.x, ty = threadIdx.y;
    #pragma unroll
    for (int s = 0; s < 4; s++) {
        int kk = ty + 8*s;
        tInv[kk][tx] = Ib[(size_t)(k0 + kk)*KTOK + j0 + tx];
    }
    if (ty == 0) dk[tx] = Ib[(size_t)(k0 + tx)*KTOK + k0 + tx];
    __syncthreads();
    #pragma unroll
    for (int s = 0; s < 4; s++) {
        int jj = ty + 8*s;
        int j = j0 + jj, k = k0 + tx;
        float a = Ab[(size_t)j*KTOK + k];
        float v = ((k != 0) ? a * dk[tx] : 0.f)
                - ((j != 0) ? a * tInv[tx][jj] : 0.f);
        tV[jj][tx] = v;
    }
    __syncthreads();
    #pragma unroll
    for (int s = 0; s < 4; s++) {
        int kk = ty + 8*s;
        out_a[(size_t)b*KTOK*(KTOK+1) + (size_t)(k0 + kk)*(KTOK+1) + (j0 + tx) + 1]
            = tV[tx][kk];
    }
}

__global__ void d0_kernel(const float* __restrict__ fid,
                          const float* __restrict__ Inv,
                          float* __restrict__ out_a) {
    int i = blockIdx.x * blockDim.x + threadIdx.x;
    if (i >= BATCH*KTOK) return;
    int b = i / KTOK, k = i % KTOK;
    out_a[(size_t)b*KTOK*(KTOK+1) + (size_t)k*(KTOK+1)]
        = fid[i] * Inv[(size_t)b*KTOK*KTOK + (size_t)k*KTOK];
}

__global__ void rank1_kernel(const float* __restrict__ out_a,
                             const float* __restrict__ exparam,
                             float* __restrict__ si) {
    int i = blockIdx.x * blockDim.x + threadIdx.x;
    if (i >= BATCH*KTOK*SEM) return;
    int c  = i % SEM;
    int bj = i / SEM;
    int b = bj / KTOK, j = bj % KTOK;
    float a0 = out_a[(size_t)b*KTOK*(KTOK+1) + (size_t)j*(KTOK+1)];
    si[i] += a0 * exparam[c];
}

// ---------------- 128x128x16 cp.async double-buffered fp32 GEMM ----------------
// Requires: M % 128 == 0, N % 128 == 0, K % 16 == 0 (true for all call sites).
#define FLAG_BIAS  1
#define FLAG_TANH  2

__global__ __launch_bounds__(256, 2)
void gemm_kernel(const float* __restrict__ A, const float* __restrict__ B,
                 float* __restrict__ C, const float* __restrict__ bias,
                 int M, int N, int Kd,
                 long long sAb, int sAm, int sAk,
                 long long sBb, int sBk, int sBn,
                 long long sCb, int sCm,
                 float alpha, float beta, int flags) {
    __shared__ float As[2][16][132];
    __shared__ float Bs[2][16][132];
    int bz = blockIdx.z;
    A += (size_t)bz * sAb;
    B += (size_t)bz * sBb;
    C += (size_t)bz * sCb;
    int m0 = blockIdx.y * 128, n0 = blockIdx.x * 128;
    int tid = threadIdx.x;
    int tx = tid & 15, ty = tid >> 4;

    const bool aK = (sAk == 1);   // A contiguous in K
    const bool bN = (sBn == 1);   // B contiguous in N
    const float* ga;
    const float* gb;
    long long gaStep, gbStep;
    int aR, aC, bR, bC;
    if (aK) { aC = tid >> 1; aR = (tid & 1) * 8;
              ga = A + (size_t)(m0 + aC) * sAm + aR; gaStep = 16; }
    else    { aR = tid >> 4; aC = (tid & 15) * 8;
              ga = A + (size_t)(m0 + aC) * sAm + (size_t)aR * sAk;
              gaStep = (long long)16 * sAk; }
    if (bN) { bR = tid >> 4; bC = (tid & 15) * 8;
              gb = B + (size_t)bR * sBk + (n0 + bC); gbStep = (long long)16 * sBk; }
    else    { bC = tid >> 1; bR = (tid & 1) * 8;
              gb = B + (size_t)(n0 + bC) * sBn + (size_t)bR * sBk;
              gbStep = (long long)16 * sBk; }

    auto issue = [&](int buf) {
        if (aK) {
            uint32_t s = smem_u32(&As[buf][aR][aC]);
            #pragma unroll
            for (int i = 0; i < 8; i++) cp_async4(s + i * 132 * 4, ga + i);
        } else {
            uint32_t s = smem_u32(&As[buf][aR][aC]);
            #pragma unroll
            for (int i = 0; i < 8; i++) cp_async4(s + i * 4, ga + (size_t)i * sAm);
        }
        if (bN) {
            uint32_t s = smem_u32(&Bs[buf][bR][bC]);
            cp_async16(s, gb);
            cp_async16(s + 16, gb + 4);
        } else {
            uint32_t s = smem_u32(&Bs[buf][bR][bC]);
            #pragma unroll
            for (int i = 0; i < 8; i++) cp_async4(s + i * 132 * 4, gb + (size_t)i * sBk);
        }
        ga += gaStep; gb += gbStep;
        cp_commit();
    };

    float acc[8][8];
    #pragma unroll
    for (int i = 0; i < 8; i++)
        #pragma unroll
        for (int j = 0; j < 8; j++) acc[i][j] = 0.f;

    int nk = Kd >> 4;
    issue(0);
    for (int kt = 0; kt < nk; kt++) {
        int cur = kt & 1;
        if (kt + 1 < nk) { issue(cur ^ 1); cp_wait<1>(); }
        else             { cp_wait<0>(); }
        __syncthreads();
        #pragma unroll
        for (int kk = 0; kk < 16; kk++) {
            float4 a0 = *(const float4*)&As[cur][kk][ty*8];
            float4 a1 = *(const float4*)&As[cur][kk][ty*8 + 4];
            float4 b0 = *(const float4*)&Bs[cur][kk][tx*8];
            float4 b1 = *(const float4*)&Bs[cur][kk][tx*8 + 4];
            float av[8] = {a0.x, a0.y, a0.z, a0.w, a1.x, a1.y, a1.z, a1.w};
            float bv[8] = {b0.x, b0.y, b0.z, b0.w, b1.x, b1.y, b1.z, b1.w};
            #pragma unroll
            for (int i = 0; i < 8; i++)
                #pragma unroll
                for (int j = 0; j < 8; j++)
                    acc[i][j] += av[i] * bv[j];
        }
        __syncthreads();
    }

    // ---- epilogue ----
    #pragma unroll
    for (int i = 0; i < 8; i++) {
        float* cp = C + (size_t)(m0 + ty*8 + i) * sCm + n0 + tx*8;
        #pragma unroll
        for (int g = 0; g < 2; g++) {
            float v0 = alpha * acc[i][4*g + 0];
            float v1 = alpha * acc[i][4*g + 1];
            float v2 = alpha * acc[i][4*g + 2];
            float v3 = alpha * acc[i][4*g + 3];
            if (beta != 0.f) {
                float4 o = *(const float4*)(cp + 4*g);
                v0 += beta * o.x; v1 += beta * o.y;
                v2 += beta * o.z; v3 += beta * o.w;
            }
            if (flags & FLAG_BIAS) {
                const float* bb = bias + n0 + tx*8 + 4*g;
                v0 += bb[0]; v1 += bb[1]; v2 += bb[2]; v3 += bb[3];
            }
            if (flags & FLAG_TANH) {
                v0 = tanhf(v0); v1 = tanhf(v1);
                v2 = tanhf(v2); v3 = tanhf(v3);
            }
            float4 w; w.x = v0; w.y = v1; w.z = v2; w.w = v3;
            *(float4*)(cp + 4*g) = w;
        }
    }
}

static inline void launch_gemm(const float* A, const float* B, float* C,
                               const float* bias,
                               int M, int N, int Kd,
                               long long sAb, int sAm, int sAk,
                               long long sBb, int sBk, int sBn,
                               long long sCb, int sCm,
                               float alpha, float beta, int flags, int batch) {
    dim3 g(N / 128, M / 128, batch);
    gemm_kernel<<<g, 256>>>(A, B, C, bias, M, N, Kd,
                            sAb, sAm, sAk, sBb, sBk, sBn, sCb, sCm,
                            alpha, beta, flags);
}

// ---------------- driver ----------------
extern "C" void kernel_launch(void* const* d_in, const int* in_sizes, int n_in,
                              void* d_out, int out_size) {
    const float* x       = (const float*)d_in[0];
    const float* Wp_w    = (const float*)d_in[1];
    const float* Wp_b    = (const float*)d_in[2];
    const float* Wc_w    = (const float*)d_in[3];
    const float* Wc_b    = (const float*)d_in[4];
    const float* fi_w    = (const float*)d_in[5];
    const float* Wa_w    = (const float*)d_in[6];
    const float* exparam = (const float*)d_in[7];
    const float* Wr_w    = (const float*)d_in[8];
    const float* Wr_b    = (const float*)d_in[9];

    float* out_r = (float*)d_out;
    float* out_a = out_r + (size_t)BATCH*KTOK*SEM;

    float *ei, *di, *uj, *uk, *vv, *Am, *gg, *cm, *fid, *si, *ci;
    float *cs, *G, *Wf, *Pvf, *Rf;
    cudaGetSymbolAddress((void**)&ei,  g_ei);
    cudaGetSymbolAddress((void**)&di,  g_di);
    cudaGetSymbolAddress((void**)&uj,  g_uj);
    cudaGetSymbolAddress((void**)&uk,  g_uk);
    cudaGetSymbolAddress((void**)&vv,  g_v);
    cudaGetSymbolAddress((void**)&Am,  g_A);
    cudaGetSymbolAddress((void**)&gg,  g_g);
    cudaGetSymbolAddress((void**)&cm,  g_cm);
    cudaGetSymbolAddress((void**)&fid, g_fid);
    cudaGetSymbolAddress((void**)&si,  g_si);
    cudaGetSymbolAddress((void**)&ci,  g_ci);
    cudaGetSymbolAddress((void**)&cs,  g_cs);
    cudaGetSymbolAddress((void**)&G,   g_G);
    cudaGetSymbolAddress((void**)&Wf,  g_Wf);
    cudaGetSymbolAddress((void**)&Pvf, g_Pvf);
    cudaGetSymbolAddress((void**)&Rf,  g_Rf);

    cudaFuncSetAttribute(pivot_inv_kernel,
                         cudaFuncAttributeMaxDynamicSharedMemorySize,
                         (NB*(NB+1) + NB) * 8);

    // 1) semantic/structural split
    split_kernel<<<(BATCH*KTOK*SEM + 255)/256, 256>>>(x, ei, di);

    // 2) u_j = tanh(d W_p + b), u_k = tanh(d W_c + b)
    launch_gemm(di, Wp_w, uj, Wp_b, BATCH*KTOK, STRD, STRD,
                0, STRD, 1, 0, STRD, 1, 0, STRD, 1.f, 0.f, FLAG_BIAS|FLAG_TANH, 1);
    launch_gemm(di, Wc_w, uk, Wc_b, BATCH*KTOK, STRD, STRD,
                0, STRD, 1, 0, STRD, 1, 0, STRD, 1.f, 0.f, FLAG_BIAS|FLAG_TANH, 1);

    // 3) v = u_k @ Wa^T
    launch_gemm(uk, Wa_w, vv, nullptr, BATCH*KTOK, STRD, STRD,
                0, STRD, 1, 0, 1, STRD, 0, STRD, 1.f, 0.f, 0, 1);

    // 4) raw root scores g = d @ fi_w
    fi_kernel<<<(BATCH*KTOK + 7)/8, 256>>>(di, fi_w, gg);

    // 5) raw bilinear scores S = u_j v^T  (batched NT GEMM)
    launch_gemm(uj, vv, Am, nullptr, KTOK, KTOK, STRD,
                (long long)KTOK*STRD, STRD, 1,
                (long long)KTOK*STRD, 1, STRD,
                (long long)KTOK*KTOK, KTOK, 1.f, 0.f, 0, BATCH);

    // 6) per-column max normalization (tree marginals are column-scale invariant)
    colmax_fid_kernel<<<(BATCH*KTOK + 255)/256, 256>>>(Am, gg, cm, fid);
    normA_kernel<<<(unsigned)(((size_t)BATCH*KTOK*KTOK + 255)/256), 256>>>(Am, cm);
    colsum_kernel<<<(BATCH*KTOK + 255)/256, 256>>>(Am, cs);

    // 7) Laplacian (fp32) into G
    build_kernel<<<(unsigned)(((size_t)BATCH*KTOK*KTOK + 255)/256), 256>>>(Am, fid, cs, G);

    // 8) in-place blocked Gauss-Jordan: G -> G^{-1}
    //    per step: Pinv = inv(G[J,J]); W = G[:,J]-E, G[:,J]=E;
    //              R = Pinv @ G[J,:]; G -= W @ R
    for (int s = 0; s < NSTEP; s++) {
        int k0 = s * NB;
        pivot_inv_kernel<<<BATCH, 512, (NB*(NB+1) + NB) * 8>>>(G, Pvf, k0);
        copyw_kernel<<<(BATCH*KTOK*NB + 255)/256, 256>>>(G, Wf, k0);
        // R = Pinv @ G[J, :]   (NB x KTOK)
        launch_gemm(Pvf, G + (size_t)k0*KTOK, Rf, nullptr, NB, KTOK, NB,
                    (long long)NB*NB, NB, 1,
                    (long long)KTOK*KTOK, KTOK, 1,
                    (long long)NB*KTOK, KTOK, 1.f, 0.f, 0, BATCH);
        // G -= W @ R           (KTOK x KTOK, rows J become R via the W-E trick)
        launch_gemm(Wf, Rf, G, nullptr, KTOK, KTOK, NB,
                    (long long)KTOK*NB, NB, 1,
                    (long long)NB*KTOK, KTOK, 1,
                    (long long)KTOK*KTOK, KTOK, -1.f, 1.f, 0, BATCH);
    }

    // 9) edge marginals -> out_a (transposed), root column d0
    marginals_kernel<<<dim3(KTOK/32, KTOK/32, BATCH), dim3(32, 8)>>>(Am, G, out_a);
    d0_kernel<<<(BATCH*KTOK + 255)/256, 256>>>(fid, G, out_a);

    // 10) si = a_ki[:,:,1:] @ e_i + a_ki[:,:,0] x exparam
    launch_gemm(out_a + 1, ei, si, nullptr, KTOK, SEM, KTOK,
                (long long)KTOK*(KTOK+1), KTOK+1, 1,
                (long long)KTOK*SEM, SEM, 1,
                (long long)KTOK*SEM, SEM, 1.f, 0.f, 0, BATCH);
    rank1_kernel<<<(BATCH*KTOK*SEM + 255)/256, 256>>>(out_a, exparam, si);

    // 11) ci = a_ik @ e_i, reading a_ik as the transpose of out_a[:,:,1:]
    launch_gemm(out_a + 1, ei, ci, nullptr, KTOK, SEM, KTOK,
                (long long)KTOK*(KTOK+1), 1, KTOK+1,
                (long long)KTOK*SEM, SEM, 1,
                (long long)KTOK*SEM, SEM, 1.f, 0.f, 0, BATCH);

    // 12) r = tanh([e|si|ci] @ Wr + b)   as 3 accumulating GEMMs
    launch_gemm(ei, Wr_w, out_r, nullptr, BATCH*KTOK, SEM, STRD,
                0, SEM, 1, 0, SEM, 1, 0, SEM, 1.f, 0.f, 0, 1);
    launch_gemm(si, Wr_w + (size_t)384*384, out_r, nullptr, BATCH*KTOK, SEM, STRD,
                0, SEM, 1, 0, SEM, 1, 0, SEM, 1.f, 1.f, 0, 1);
    launch_gemm(ci, Wr_w + (size_t)768*384, out_r, Wr_b, BATCH*KTOK, SEM, STRD,
                0, SEM, 1, 0, SEM, 1, 0, SEM, 1.f, 1.f, FLAG_BIAS|FLAG_TANH, 1);
}

// round 8
// speedup vs baseline: 4.3990x; 1.0006x over previous
#include <cuda_runtime.h>
#include <math.h>
#include <stdint.h>

#define BATCH 16
#define KTOK  1024
#define DD    768
#define SEM   384
#define STRD  384
#define NB    128
#define NSTEP (KTOK/NB)

// ---------------- device scratch (bss, no runtime allocation) ----------------
__device__ float  g_ei [BATCH*KTOK*SEM];
__device__ float  g_di [BATCH*KTOK*STRD];
__device__ float  g_uj [BATCH*KTOK*STRD];
__device__ float  g_uk [BATCH*KTOK*STRD];
__device__ float  g_v  [BATCH*KTOK*STRD];
__device__ float  g_A  [(size_t)BATCH*KTOK*KTOK];   // raw scores, then normalized A
__device__ float  g_g  [BATCH*KTOK];                // raw root scores (pre-exp)
__device__ float  g_cm [BATCH*KTOK];                // per-column max
__device__ float  g_fid[BATCH*KTOK];                // normalized root weight exp(g-m)
__device__ float  g_cs [BATCH*KTOK];                // column sums
__device__ float  g_G  [(size_t)BATCH*KTOK*KTOK];   // Laplacian -> in-place inverse
__device__ float  g_Wf [BATCH*KTOK*NB];
__device__ float  g_Pvf[BATCH*NB*NB];
__device__ float  g_Rf [BATCH*NB*KTOK];
__device__ float  g_si [BATCH*KTOK*SEM];
__device__ float  g_ci [BATCH*KTOK*SEM];

// ---------------- cp.async helpers ----------------
__device__ __forceinline__ uint32_t smem_u32(const void* p) {
    return (uint32_t)__cvta_generic_to_shared(p);
}
__device__ __forceinline__ void cp_async4(uint32_t s, const float* g) {
    asm volatile("cp.async.ca.shared.global [%0], [%1], 4;" :: "r"(s), "l"(g));
}
__device__ __forceinline__ void cp_async16(uint32_t s, const float* g) {
    asm volatile("cp.async.cg.shared.global [%0], [%1], 16;" :: "r"(s), "l"(g));
}
__device__ __forceinline__ void cp_commit() {
    asm volatile("cp.async.commit_group;");
}
template<int N> __device__ __forceinline__ void cp_wait() {
    asm volatile("cp.async.wait_group %0;" :: "n"(N));
}

// ---------------- elementwise kernels ----------------
__global__ void split_kernel(const float* __restrict__ x,
                             float* __restrict__ ei, float* __restrict__ di) {
    int i = blockIdx.x * blockDim.x + threadIdx.x;
    if (i >= BATCH*KTOK*SEM) return;
    int c  = i % SEM;
    int bk = i / SEM;
    const float* xr = x + (size_t)bk * DD;
    ei[i] = xr[c < 192 ? c       : c + 192];
    di[i] = xr[c < 192 ? c + 192 : c + 384];
}

__global__ void fi_kernel(const float* __restrict__ di,
                          const float* __restrict__ fw,
                          float* __restrict__ g) {
    int row  = blockIdx.x * 8 + (threadIdx.x >> 5);
    int lane = threadIdx.x & 31;
    if (row >= BATCH*KTOK) return;
    const float* d = di + (size_t)row * STRD;
    float s = 0.f;
    for (int c = lane; c < STRD; c += 32) s += d[c] * fw[c];
    #pragma unroll
    for (int o = 16; o; o >>= 1) s += __shfl_xor_sync(0xffffffffu, s, o);
    if (lane == 0) g[row] = s;
}

// m_k = max(g_k, max_{j!=k} S[j,k]); fid = exp(g - m)
__global__ void colmax_fid_kernel(const float* __restrict__ S,
                                  const float* __restrict__ g,
                                  float* __restrict__ cm,
                                  float* __restrict__ fid) {
    int i = blockIdx.x * blockDim.x + threadIdx.x;
    if (i >= BATCH*KTOK) return;
    int b = i / KTOK, k = i % KTOK;
    const float* Sb = S + (size_t)b*KTOK*KTOK + k;
    float m = g[i];
    for (int j = 0; j < KTOK; j++) {
        if (j == k) continue;
        m = fmaxf(m, Sb[(size_t)j*KTOK]);
    }
    cm[i]  = m;
    fid[i] = expf(g[i] - m);
}

// A[j,k] = (j==k) ? 0 : exp(S - m_k)  (in place over S)
__global__ void normA_kernel(float* __restrict__ S, const float* __restrict__ cm) {
    size_t i = (size_t)blockIdx.x * blockDim.x + threadIdx.x;
    if (i >= (size_t)BATCH*KTOK*KTOK) return;
    int k = (int)(i % KTOK);
    size_t t = i / KTOK;
    int j = (int)(t % KTOK);
    int b = (int)(t / KTOK);
    S[i] = (j == k) ? 0.f : expf(S[i] - cm[b*KTOK + k]);
}

__global__ void colsum_kernel(const float* __restrict__ A, float* __restrict__ cs) {
    int i = blockIdx.x * blockDim.x + threadIdx.x;
    if (i >= BATCH*KTOK) return;
    int b = i / KTOK, k = i % KTOK;
    const float* Ab = A + (size_t)b*KTOK*KTOK + k;
    double s = 0.0;
    for (int j = 0; j < KTOK; j++) s += (double)Ab[(size_t)j*KTOK];
    cs[i] = (float)s;
}

__global__ void build_kernel(const float* __restrict__ A,
                             const float* __restrict__ fid,
                             const float* __restrict__ cs,
                             float* __restrict__ G) {
    size_t i = (size_t)blockIdx.x * blockDim.x + threadIdx.x;
    if (i >= (size_t)BATCH*KTOK*KTOK) return;
    int k = (int)(i % KTOK);
    size_t t = i / KTOK;
    int j = (int)(t % KTOK);
    int b = (int)(t / KTOK);
    float v;
    if (j == 0) v = fid[b*KTOK + k];
    else        v = -A[i] + (j == k ? cs[b*KTOK + k] : 0.f);
    G[i] = v;
}

// W = G[:, J] - E_J  and  G[:, J] := E_J   (in-place GJ column extraction)
__global__ void copyw_kernel(float* __restrict__ G, float* __restrict__ W, int k0) {
    int i = blockIdx.x * blockDim.x + threadIdx.x;
    if (i >= BATCH*KTOK*NB) return;
    int t = i % NB;
    int r = (i / NB) % KTOK;
    int b = i / (NB*KTOK);
    size_t gi = (size_t)b*KTOK*KTOK + (size_t)r*KTOK + k0 + t;
    float w = G[gi];
    bool dg = (r == k0 + t);
    W[i]  = dg ? w - 1.f : w;
    G[gi] = dg ? 1.f : 0.f;
}

// in-smem fp64 Gauss-Jordan inversion of the 128x128 pivot block (fp32 in/out)
__global__ void pivot_inv_kernel(const float* __restrict__ G,
                                 float* __restrict__ Pinv, int k0) {
    extern __shared__ double P[];           // NB x (NB+1), then rowbuf[NB]
    double* rowbuf = P + NB*(NB+1);
    int b = blockIdx.x;
    int tid = threadIdx.x;
    const float* Gb = G + (size_t)b*KTOK*KTOK;
    for (int i = tid; i < NB*NB; i += blockDim.x) {
        int r = i >> 7, c = i & 127;
        P[r*129 + c] = (double)Gb[(size_t)(k0 + r)*KTOK + k0 + c];
    }
    __syncthreads();
    int r  = tid >> 2;                      // 512 threads -> 4 threads per row
    int c0 = (tid & 3) * 32;
    for (int j = 0; j < NB; j++) {
        double pinv = 1.0 / P[j*129 + j];
        double f    = P[r*129 + j];
        if (tid < NB) rowbuf[tid] = (tid == j) ? pinv : P[j*129 + tid] * pinv;
        __syncthreads();
        if (r == j) {
            for (int c = c0; c < c0 + 32; c++) P[j*129 + c] = rowbuf[c];
        } else {
            for (int c = c0; c < c0 + 32; c++) {
                P[r*129 + c] = (c == j) ? (-f * pinv)
                                        : fma(-f, rowbuf[c], P[r*129 + c]);
            }
        }
        __syncthreads();
    }
    for (int i = tid; i < NB*NB; i += blockDim.x) {
        int rr = i >> 7, cc = i & 127;
        Pinv[(size_t)b*NB*NB + i] = (float)P[rr*129 + cc];
    }
}

// edge marginals -> transposed store of a_ki into output buffer
__global__ void marginals_kernel(const float* __restrict__ A,
                                 const float* __restrict__ Inv,
                                 float* __restrict__ out_a) {
    __shared__ float tInv[32][33];
    __shared__ float tV[32][33];
    __shared__ float dk[32];
    int b  = blockIdx.z;
    int k0 = blockIdx.x * 32;
    int j0 = blockIdx.y * 32;
    const float* Ib = Inv + (size_t)b*KTOK*KTOK;
    const float* Ab = A   + (size_t)b*KTOK*KTOK;
    int tx = threadIdx.x, ty = threadIdx.y;
    #pragma unroll
    for (int s = 0; s < 4; s++) {
        int kk = ty + 8*s;
        tInv[kk][tx] = Ib[(size_t)(k0 + kk)*KTOK + j0 + tx];
    }
    if (ty == 0) dk[tx] = Ib[(size_t)(k0 + tx)*KTOK + k0 + tx];
    __syncthreads();
    #pragma unroll
    for (int s = 0; s < 4; s++) {
        int jj = ty + 8*s;
        int j = j0 + jj, k = k0 + tx;
        float a = Ab[(size_t)j*KTOK + k];
        float v = ((k != 0) ? a * dk[tx] : 0.f)
                - ((j != 0) ? a * tInv[tx][jj] : 0.f);
        tV[jj][tx] = v;
    }
    __syncthreads();
    #pragma unroll
    for (int s = 0; s < 4; s++) {
        int kk = ty + 8*s;
        out_a[(size_t)b*KTOK*(KTOK+1) + (size_t)(k0 + kk)*(KTOK+1) + (j0 + tx) + 1]
            = tV[tx][kk];
    }
}

__global__ void d0_kernel(const float* __restrict__ fid,
                          const float* __restrict__ Inv,
                          float* __restrict__ out_a) {
    int i = blockIdx.x * blockDim.x + threadIdx.x;
    if (i >= BATCH*KTOK) return;
    int b = i / KTOK, k = i % KTOK;
    out_a[(size_t)b*KTOK*(KTOK+1) + (size_t)k*(KTOK+1)]
        = fid[i] * Inv[(size_t)b*KTOK*KTOK + (size_t)k*KTOK];
}

__global__ void rank1_kernel(const float* __restrict__ out_a,
                             const float* __restrict__ exparam,
                             float* __restrict__ si) {
    int i = blockIdx.x * blockDim.x + threadIdx.x;
    if (i >= BATCH*KTOK*SEM) return;
    int c  = i % SEM;
    int bj = i / SEM;
    int b = bj / KTOK, j = bj % KTOK;
    float a0 = out_a[(size_t)b*KTOK*(KTOK+1) + (size_t)j*(KTOK+1)];
    si[i] += a0 * exparam[c];
}

// ---------------- 128x128x16 cp.async + reg-pipelined fp32 GEMM ----------------
// Requires: M % 128 == 0, N % 128 == 0, K % 16 == 0 (true for all call sites).
#define FLAG_BIAS  1
#define FLAG_TANH  2

__global__ __launch_bounds__(256, 2)
void gemm_kernel(const float* __restrict__ A, const float* __restrict__ B,
                 float* __restrict__ C, const float* __restrict__ bias,
                 int M, int N, int Kd,
                 long long sAb, int sAm, int sAk,
                 long long sBb, int sBk, int sBn,
                 long long sCb, int sCm,
                 float alpha, float beta, int flags) {
    __shared__ float As[2][16][132];
    __shared__ float Bs[2][16][132];
    int bz = blockIdx.z;
    A += (size_t)bz * sAb;
    B += (size_t)bz * sBb;
    C += (size_t)bz * sCb;
    int m0 = blockIdx.y * 128, n0 = blockIdx.x * 128;
    int tid = threadIdx.x;
    int tx = tid & 15, ty = tid >> 4;

    const bool aK = (sAk == 1);   // A contiguous in K
    const bool bN = (sBn == 1);   // B contiguous in N
    const float* ga;
    const float* gb;
    long long gaStep, gbStep;
    int aR, aC, bR, bC;
    if (aK) { aC = tid >> 1; aR = (tid & 1) * 8;
              ga = A + (size_t)(m0 + aC) * sAm + aR; gaStep = 16; }
    else    { aR = tid >> 4; aC = (tid & 15) * 8;
              ga = A + (size_t)(m0 + aC) * sAm + (size_t)aR * sAk;
              gaStep = (long long)16 * sAk; }
    if (bN) { bR = tid >> 4; bC = (tid & 15) * 8;
              gb = B + (size_t)bR * sBk + (n0 + bC); gbStep = (long long)16 * sBk; }
    else    { bC = tid >> 1; bR = (tid & 1) * 8;
              gb = B + (size_t)(n0 + bC) * sBn + (size_t)bR * sBk;
              gbStep = (long long)16 * sBk; }

    auto issue = [&](int buf) {
        if (aK) {
            uint32_t s = smem_u32(&As[buf][aR][aC]);
            #pragma unroll
            for (int i = 0; i < 8; i++) cp_async4(s + i * 132 * 4, ga + i);
        } else {
            uint32_t s = smem_u32(&As[buf][aR][aC]);
            #pragma unroll
            for (int i = 0; i < 8; i++) cp_async4(s + i * 4, ga + (size_t)i * sAm);
        }
        if (bN) {
            uint32_t s = smem_u32(&Bs[buf][bR][bC]);
            cp_async16(s, gb);
            cp_async16(s + 16, gb + 4);
        } else {
            uint32_t s = smem_u32(&Bs[buf][bR][bC]);
            #pragma unroll
            for (int i = 0; i < 8; i++) cp_async4(s + i * 132 * 4, gb + (size_t)i * sBk);
        }
        ga += gaStep; gb += gbStep;
        cp_commit();
    };

    float acc[8][8];
    #pragma unroll
    for (int i = 0; i < 8; i++)
        #pragma unroll
        for (int j = 0; j < 8; j++) acc[i][j] = 0.f;

    float af[2][8], bf[2][8];

    int nk = Kd >> 4;
    issue(0);
    for (int kt = 0; kt < nk; kt++) {
        int cur = kt & 1;
        if (kt + 1 < nk) { issue(cur ^ 1); cp_wait<1>(); }
        else             { cp_wait<0>(); }
        __syncthreads();

        // preload fragment for kk = 0
        {
            float4 a0 = *(const float4*)&As[cur][0][ty*8];
            float4 a1 = *(const float4*)&As[cur][0][ty*8 + 4];
            float4 b0 = *(const float4*)&Bs[cur][0][tx*8];
            float4 b1 = *(const float4*)&Bs[cur][0][tx*8 + 4];
            af[0][0]=a0.x; af[0][1]=a0.y; af[0][2]=a0.z; af[0][3]=a0.w;
            af[0][4]=a1.x; af[0][5]=a1.y; af[0][6]=a1.z; af[0][7]=a1.w;
            bf[0][0]=b0.x; bf[0][1]=b0.y; bf[0][2]=b0.z; bf[0][3]=b0.w;
            bf[0][4]=b1.x; bf[0][5]=b1.y; bf[0][6]=b1.z; bf[0][7]=b1.w;
        }
        #pragma unroll
        for (int kk = 0; kk < 16; kk++) {
            int cs = kk & 1, ns = cs ^ 1;
            if (kk < 15) {   // prefetch kk+1 fragment while computing kk
                float4 a0 = *(const float4*)&As[cur][kk+1][ty*8];
                float4 a1 = *(const float4*)&As[cur][kk+1][ty*8 + 4];
                float4 b0 = *(const float4*)&Bs[cur][kk+1][tx*8];
                float4 b1 = *(const float4*)&Bs[cur][kk+1][tx*8 + 4];
                af[ns][0]=a0.x; af[ns][1]=a0.y; af[ns][2]=a0.z; af[ns][3]=a0.w;
                af[ns][4]=a1.x; af[ns][5]=a1.y; af[ns][6]=a1.z; af[ns][7]=a1.w;
                bf[ns][0]=b0.x; bf[ns][1]=b0.y; bf[ns][2]=b0.z; bf[ns][3]=b0.w;
                bf[ns][4]=b1.x; bf[ns][5]=b1.y; bf[ns][6]=b1.z; bf[ns][7]=b1.w;
            }
            #pragma unroll
            for (int i = 0; i < 8; i++)
                #pragma unroll
                for (int j = 0; j < 8; j++)
                    acc[i][j] += af[cs][i] * bf[cs][j];
        }
        __syncthreads();
    }

    // ---- epilogue ----
    #pragma unroll
    for (int i = 0; i < 8; i++) {
        float* cp = C + (size_t)(m0 + ty*8 + i) * sCm + n0 + tx*8;
        #pragma unroll
        for (int g = 0; g < 2; g++) {
            float v0 = alpha * acc[i][4*g + 0];
            float v1 = alpha * acc[i][4*g + 1];
            float v2 = alpha * acc[i][4*g + 2];
            float v3 = alpha * acc[i][4*g + 3];
            if (beta != 0.f) {
                float4 o = *(const float4*)(cp + 4*g);
                v0 += beta * o.x; v1 += beta * o.y;
                v2 += beta * o.z; v3 += beta * o.w;
            }
            if (flags & FLAG_BIAS) {
                const float* bb = bias + n0 + tx*8 + 4*g;
                v0 += bb[0]; v1 += bb[1]; v2 += bb[2]; v3 += bb[3];
            }
            if (flags & FLAG_TANH) {
                v0 = tanhf(v0); v1 = tanhf(v1);
                v2 = tanhf(v2); v3 = tanhf(v3);
            }
            float4 w; w.x = v0; w.y = v1; w.z = v2; w.w = v3;
            *(float4*)(cp + 4*g) = w;
        }
    }
}

static inline void launch_gemm(const float* A, const float* B, float* C,
                               const float* bias,
                               int M, int N, int Kd,
                               long long sAb, int sAm, int sAk,
                               long long sBb, int sBk, int sBn,
                               long long sCb, int sCm,
                               float alpha, float beta, int flags, int batch) {
    dim3 g(N / 128, M / 128, batch);
    gemm_kernel<<<g, 256>>>(A, B, C, bias, M, N, Kd,
                            sAb, sAm, sAk, sBb, sBk, sBn, sCb, sCm,
                            alpha, beta, flags);
}

// ---------------- driver ----------------
extern "C" void kernel_launch(void* const* d_in, const int* in_sizes, int n_in,
                              void* d_out, int out_size) {
    const float* x       = (const float*)d_in[0];
    const float* Wp_w    = (const float*)d_in[1];
    const float* Wp_b    = (const float*)d_in[2];
    const float* Wc_w    = (const float*)d_in[3];
    const float* Wc_b    = (const float*)d_in[4];
    const float* fi_w    = (const float*)d_in[5];
    const float* Wa_w    = (const float*)d_in[6];
    const float* exparam = (const float*)d_in[7];
    const float* Wr_w    = (const float*)d_in[8];
    const float* Wr_b    = (const float*)d_in[9];

    float* out_r = (float*)d_out;
    float* out_a = out_r + (size_t)BATCH*KTOK*SEM;

    float *ei, *di, *uj, *uk, *vv, *Am, *gg, *cm, *fid, *si, *ci;
    float *cs, *G, *Wf, *Pvf, *Rf;
    cudaGetSymbolAddress((void**)&ei,  g_ei);
    cudaGetSymbolAddress((void**)&di,  g_di);
    cudaGetSymbolAddress((void**)&uj,  g_uj);
    cudaGetSymbolAddress((void**)&uk,  g_uk);
    cudaGetSymbolAddress((void**)&vv,  g_v);
    cudaGetSymbolAddress((void**)&Am,  g_A);
    cudaGetSymbolAddress((void**)&gg,  g_g);
    cudaGetSymbolAddress((void**)&cm,  g_cm);
    cudaGetSymbolAddress((void**)&fid, g_fid);
    cudaGetSymbolAddress((void**)&si,  g_si);
    cudaGetSymbolAddress((void**)&ci,  g_ci);
    cudaGetSymbolAddress((void**)&cs,  g_cs);
    cudaGetSymbolAddress((void**)&G,   g_G);
    cudaGetSymbolAddress((void**)&Wf,  g_Wf);
    cudaGetSymbolAddress((void**)&Pvf, g_Pvf);
    cudaGetSymbolAddress((void**)&Rf,  g_Rf);

    cudaFuncSetAttribute(pivot_inv_kernel,
                         cudaFuncAttributeMaxDynamicSharedMemorySize,
                         (NB*(NB+1) + NB) * 8);

    // 1) semantic/structural split
    split_kernel<<<(BATCH*KTOK*SEM + 255)/256, 256>>>(x, ei, di);

    // 2) u_j = tanh(d W_p + b), u_k = tanh(d W_c + b)
    launch_gemm(di, Wp_w, uj, Wp_b, BATCH*KTOK, STRD, STRD,
                0, STRD, 1, 0, STRD, 1, 0, STRD, 1.f, 0.f, FLAG_BIAS|FLAG_TANH, 1);
    launch_gemm(di, Wc_w, uk, Wc_b, BATCH*KTOK, STRD, STRD,
                0, STRD, 1, 0, STRD, 1, 0, STRD, 1.f, 0.f, FLAG_BIAS|FLAG_TANH, 1);

    // 3) v = u_k @ Wa^T
    launch_gemm(uk, Wa_w, vv, nullptr, BATCH*KTOK, STRD, STRD,
                0, STRD, 1, 0, 1, STRD, 0, STRD, 1.f, 0.f, 0, 1);

    // 4) raw root scores g = d @ fi_w
    fi_kernel<<<(BATCH*KTOK + 7)/8, 256>>>(di, fi_w, gg);

    // 5) raw bilinear scores S = u_j v^T  (batched NT GEMM)
    launch_gemm(uj, vv, Am, nullptr, KTOK, KTOK, STRD,
                (long long)KTOK*STRD, STRD, 1,
                (long long)KTOK*STRD, 1, STRD,
                (long long)KTOK*KTOK, KTOK, 1.f, 0.f, 0, BATCH);

    // 6) per-column max normalization (tree marginals are column-scale invariant)
    colmax_fid_kernel<<<(BATCH*KTOK + 255)/256, 256>>>(Am, gg, cm, fid);
    normA_kernel<<<(unsigned)(((size_t)BATCH*KTOK*KTOK + 255)/256), 256>>>(Am, cm);
    colsum_kernel<<<(BATCH*KTOK + 255)/256, 256>>>(Am, cs);

    // 7) Laplacian (fp32) into G
    build_kernel<<<(unsigned)(((size_t)BATCH*KTOK*KTOK + 255)/256), 256>>>(Am, fid, cs, G);

    // 8) in-place blocked Gauss-Jordan: G -> G^{-1}
    for (int s = 0; s < NSTEP; s++) {
        int k0 = s * NB;
        pivot_inv_kernel<<<BATCH, 512, (NB*(NB+1) + NB) * 8>>>(G, Pvf, k0);
        copyw_kernel<<<(BATCH*KTOK*NB + 255)/256, 256>>>(G, Wf, k0);
        // R = Pinv @ G[J, :]   (NB x KTOK)
        launch_gemm(Pvf, G + (size_t)k0*KTOK, Rf, nullptr, NB, KTOK, NB,
                    (long long)NB*NB, NB, 1,
                    (long long)KTOK*KTOK, KTOK, 1,
                    (long long)NB*KTOK, KTOK, 1.f, 0.f, 0, BATCH);
        // G -= W @ R           (KTOK x KTOK)
        launch_gemm(Wf, Rf, G, nullptr, KTOK, KTOK, NB,
                    (long long)KTOK*NB, NB, 1,
                    (long long)NB*KTOK, KTOK, 1,
                    (long long)KTOK*KTOK, KTOK, -1.f, 1.f, 0, BATCH);
    }

    // 9) edge marginals -> out_a (transposed), root column d0
    marginals_kernel<<<dim3(KTOK/32, KTOK/32, BATCH), dim3(32, 8)>>>(Am, G, out_a);
    d0_kernel<<<(BATCH*KTOK + 255)/256, 256>>>(fid, G, out_a);

    // 10) si = a_ki[:,:,1:] @ e_i + a_ki[:,:,0] x exparam
    launch_gemm(out_a + 1, ei, si, nullptr, KTOK, SEM, KTOK,
                (long long)KTOK*(KTOK+1), KTOK+1, 1,
                (long long)KTOK*SEM, SEM, 1,
                (long long)KTOK*SEM, SEM, 1.f, 0.f, 0, BATCH);
    rank1_kernel<<<(BATCH*KTOK*SEM + 255)/256, 256>>>(out_a, exparam, si);

    // 11) ci = a_ik @ e_i, reading a_ik as the transpose of out_a[:,:,1:]
    launch_gemm(out_a + 1, ei, ci, nullptr, KTOK, SEM, KTOK,
                (long long)KTOK*(KTOK+1), 1, KTOK+1,
                (long long)KTOK*SEM, SEM, 1,
                (long long)KTOK*SEM, SEM, 1.f, 0.f, 0, BATCH);

    // 12) r = tanh([e|si|ci] @ Wr + b)   as 3 accumulating GEMMs
    launch_gemm(ei, Wr_w, out_r, nullptr, BATCH*KTOK, SEM, STRD,
                0, SEM, 1, 0, SEM, 1, 0, SEM, 1.f, 0.f, 0, 1);
    launch_gemm(si, Wr_w + (size_t)384*384, out_r, nullptr, BATCH*KTOK, SEM, STRD,
                0, SEM, 1, 0, SEM, 1, 0, SEM, 1.f, 1.f, 0, 1);
    launch_gemm(ci, Wr_w + (size_t)768*384, out_r, Wr_b, BATCH*KTOK, SEM, STRD,
                0, SEM, 1, 0, SEM, 1, 0, SEM, 1.f, 1.f, FLAG_BIAS|FLAG_TANH, 1);
}

// round 10
// speedup vs baseline: 4.5051x; 1.0241x over previous
#include <cuda_runtime.h>
#include <math.h>
#include <stdint.h>

#define BATCH 16
#define KTOK  1024
#define DD    768
#define SEM   384
#define STRD  384
#define NB    128
#define NSTEP (KTOK/NB)
#define JP    16              // column-reduction parts
#define ROWSP (KTOK/JP)       // 64 rows per part
#define ESCW  (3*SEM)         // 1152 packed [e|s|c] row width

// ---------------- device scratch (bss, no runtime allocation) ----------------
__device__ float  g_esc [(size_t)BATCH*KTOK*ESCW];   // [e | s | c] packed
__device__ float  g_di  [BATCH*KTOK*STRD];
__device__ float  g_ujk [2*BATCH*KTOK*STRD];         // u_j then u_k
__device__ float  g_v   [BATCH*KTOK*STRD];
__device__ float  g_A   [(size_t)BATCH*KTOK*KTOK];   // raw scores -> normalized A
__device__ float  g_g   [BATCH*KTOK];
__device__ float  g_cm  [BATCH*KTOK];
__device__ float  g_fid [BATCH*KTOK];
__device__ float  g_cs  [BATCH*KTOK];
__device__ float  g_pmax[JP*BATCH*KTOK];
__device__ float  g_psum[JP*BATCH*KTOK];
__device__ float  g_G   [(size_t)BATCH*KTOK*KTOK];   // Laplacian -> in-place inverse
__device__ float  g_Wf  [BATCH*KTOK*NB];
__device__ float  g_Pvf [BATCH*NB*NB];
__device__ float  g_Rf  [BATCH*NB*KTOK];
__device__ float  g_Wcat[2*STRD*STRD];
__device__ float  g_bcat[2*STRD];

// ---------------- cp.async helpers ----------------
__device__ __forceinline__ uint32_t smem_u32(const void* p) {
    return (uint32_t)__cvta_generic_to_shared(p);
}
__device__ __forceinline__ void cp_async4(uint32_t s, const float* g) {
    asm volatile("cp.async.ca.shared.global [%0], [%1], 4;" :: "r"(s), "l"(g));
}
__device__ __forceinline__ void cp_async16(uint32_t s, const float* g) {
    asm volatile("cp.async.cg.shared.global [%0], [%1], 16;" :: "r"(s), "l"(g));
}
__device__ __forceinline__ void cp_commit() {
    asm volatile("cp.async.commit_group;");
}
template<int N> __device__ __forceinline__ void cp_wait() {
    asm volatile("cp.async.wait_group %0;" :: "n"(N));
}

// ---------------- elementwise kernels ----------------
__global__ void split_kernel(const float* __restrict__ x,
                             float* __restrict__ esc, float* __restrict__ di) {
    int i = blockIdx.x * blockDim.x + threadIdx.x;
    if (i >= BATCH*KTOK*SEM) return;
    int c  = i % SEM;
    int bk = i / SEM;
    const float* xr = x + (size_t)bk * DD;
    esc[(size_t)bk*ESCW + c] = xr[c < 192 ? c       : c + 192];
    di[i]                    = xr[c < 192 ? c + 192 : c + 384];
}

__global__ void wcat_kernel(const float* __restrict__ Wp_w, const float* __restrict__ Wp_b,
                            const float* __restrict__ Wc_w, const float* __restrict__ Wc_b,
                            float* __restrict__ Wcat, float* __restrict__ bcat) {
    int i = blockIdx.x * blockDim.x + threadIdx.x;
    if (i < STRD*STRD) { Wcat[i] = Wp_w[i]; Wcat[STRD*STRD + i] = Wc_w[i]; }
    if (i < STRD)      { bcat[i] = Wp_b[i]; bcat[STRD + i]      = Wc_b[i]; }
}

__global__ void fi_kernel(const float* __restrict__ di,
                          const float* __restrict__ fw,
                          float* __restrict__ g) {
    int row  = blockIdx.x * 8 + (threadIdx.x >> 5);
    int lane = threadIdx.x & 31;
    if (row >= BATCH*KTOK) return;
    const float* d = di + (size_t)row * STRD;
    float s = 0.f;
    for (int c = lane; c < STRD; c += 32) s += d[c] * fw[c];
    #pragma unroll
    for (int o = 16; o; o >>= 1) s += __shfl_xor_sync(0xffffffffu, s, o);
    if (lane == 0) g[row] = s;
}

// phase 1: partial per-column max over a 64-row slab
__global__ void colmax_part_kernel(const float* __restrict__ S,
                                   float* __restrict__ pmax) {
    int i  = blockIdx.x * blockDim.x + threadIdx.x;   // (b,k)
    int jp = blockIdx.y;
    if (i >= BATCH*KTOK) return;
    int b = i / KTOK, k = i % KTOK;
    const float* Sb = S + (size_t)b*KTOK*KTOK + k;
    float m = -3.4e38f;
    int j0 = jp * ROWSP;
    #pragma unroll 4
    for (int j = j0; j < j0 + ROWSP; j++) {
        float v = Sb[(size_t)j*KTOK];
        if (j != k) m = fmaxf(m, v);
    }
    pmax[(size_t)jp*BATCH*KTOK + i] = m;
}

// phase 2: cm = max(g, partials); fid = exp(g - cm)
__global__ void colmax_reduce_kernel(const float* __restrict__ pmax,
                                     const float* __restrict__ g,
                                     float* __restrict__ cm,
                                     float* __restrict__ fid) {
    int i = blockIdx.x * blockDim.x + threadIdx.x;
    if (i >= BATCH*KTOK) return;
    float m = g[i];
    #pragma unroll
    for (int jp = 0; jp < JP; jp++)
        m = fmaxf(m, pmax[(size_t)jp*BATCH*KTOK + i]);
    cm[i]  = m;
    fid[i] = expf(g[i] - m);
}

// phase 1: normalize+exp in place, partial column sums over a 64-row slab
__global__ void normA_colsum_part_kernel(float* __restrict__ S,
                                         const float* __restrict__ cm,
                                         float* __restrict__ psum) {
    int i  = blockIdx.x * blockDim.x + threadIdx.x;
    int jp = blockIdx.y;
    if (i >= BATCH*KTOK) return;
    int b = i / KTOK, k = i % KTOK;
    float m = cm[i];
    float* Sb = S + (size_t)b*KTOK*KTOK + k;
    float s = 0.f;
    int j0 = jp * ROWSP;
    for (int j = j0; j < j0 + ROWSP; j++) {
        float a = (j == k) ? 0.f : expf(Sb[(size_t)j*KTOK] - m);
        Sb[(size_t)j*KTOK] = a;
        s += a;
    }
    psum[(size_t)jp*BATCH*KTOK + i] = s;
}

__global__ void colsum_reduce_kernel(const float* __restrict__ psum,
                                     float* __restrict__ cs) {
    int i = blockIdx.x * blockDim.x + threadIdx.x;
    if (i >= BATCH*KTOK) return;
    double s = 0.0;
    #pragma unroll
    for (int jp = 0; jp < JP; jp++)
        s += (double)psum[(size_t)jp*BATCH*KTOK + i];
    cs[i] = (float)s;
}

__global__ void build_kernel(const float* __restrict__ A,
                             const float* __restrict__ fid,
                             const float* __restrict__ cs,
                             float* __restrict__ G) {
    size_t i = (size_t)blockIdx.x * blockDim.x + threadIdx.x;
    if (i >= (size_t)BATCH*KTOK*KTOK) return;
    int k = (int)(i % KTOK);
    size_t t = i / KTOK;
    int j = (int)(t % KTOK);
    int b = (int)(t / KTOK);
    float v;
    if (j == 0) v = fid[b*KTOK + k];
    else        v = -A[i] + (j == k ? cs[b*KTOK + k] : 0.f);
    G[i] = v;
}

// W = G[:, J] - E_J  and  G[:, J] := E_J   (in-place GJ column extraction)
__global__ void copyw_kernel(float* __restrict__ G, float* __restrict__ W, int k0) {
    int i = blockIdx.x * blockDim.x + threadIdx.x;
    if (i >= BATCH*KTOK*NB) return;
    int t = i % NB;
    int r = (i / NB) % KTOK;
    int b = i / (NB*KTOK);
    size_t gi = (size_t)b*KTOK*KTOK + (size_t)r*KTOK + k0 + t;
    float w = G[gi];
    bool dg = (r == k0 + t);
    W[i]  = dg ? w - 1.f : w;
    G[gi] = dg ? 1.f : 0.f;
}

// in-smem fp64 Gauss-Jordan inversion of the 128x128 pivot block (fp32 in/out)
__global__ void pivot_inv_kernel(const float* __restrict__ G,
                                 float* __restrict__ Pinv, int k0) {
    extern __shared__ double P[];           // NB x (NB+1), then rowbuf[NB]
    double* rowbuf = P + NB*(NB+1);
    int b = blockIdx.x;
    int tid = threadIdx.x;
    const float* Gb = G + (size_t)b*KTOK*KTOK;
    for (int i = tid; i < NB*NB; i += blockDim.x) {
        int r = i >> 7, c = i & 127;
        P[r*129 + c] = (double)Gb[(size_t)(k0 + r)*KTOK + k0 + c];
    }
    __syncthreads();
    int r  = tid >> 2;                      // 512 threads -> 4 threads per row
    int c0 = (tid & 3) * 32;
    for (int j = 0; j < NB; j++) {
        double pinv = 1.0 / P[j*129 + j];
        double f    = P[r*129 + j];
        if (tid < NB) rowbuf[tid] = (tid == j) ? pinv : P[j*129 + tid] * pinv;
        __syncthreads();
        if (r == j) {
            for (int c = c0; c < c0 + 32; c++) P[j*129 + c] = rowbuf[c];
        } else {
            for (int c = c0; c < c0 + 32; c++) {
                P[r*129 + c] = (c == j) ? (-f * pinv)
                                        : fma(-f, rowbuf[c], P[r*129 + c]);
            }
        }
        __syncthreads();
    }
    for (int i = tid; i < NB*NB; i += blockDim.x) {
        int rr = i >> 7, cc = i & 127;
        Pinv[(size_t)b*NB*NB + i] = (float)P[rr*129 + cc];
    }
}

// edge marginals -> transposed store of a_ki into output buffer
__global__ void marginals_kernel(const float* __restrict__ A,
                                 const float* __restrict__ Inv,
                                 float* __restrict__ out_a) {
    __shared__ float tInv[32][33];
    __shared__ float tV[32][33];
    __shared__ float dk[32];
    int b  = blockIdx.z;
    int k0 = blockIdx.x * 32;
    int j0 = blockIdx.y * 32;
    const float* Ib = Inv + (size_t)b*KTOK*KTOK;
    const float* Ab = A   + (size_t)b*KTOK*KTOK;
    int tx = threadIdx.x, ty = threadIdx.y;
    #pragma unroll
    for (int s = 0; s < 4; s++) {
        int kk = ty + 8*s;
        tInv[kk][tx] = Ib[(size_t)(k0 + kk)*KTOK + j0 + tx];
    }
    if (ty == 0) dk[tx] = Ib[(size_t)(k0 + tx)*KTOK + k0 + tx];
    __syncthreads();
    #pragma unroll
    for (int s = 0; s < 4; s++) {
        int jj = ty + 8*s;
        int j = j0 + jj, k = k0 + tx;
        float a = Ab[(size_t)j*KTOK + k];
        float v = ((k != 0) ? a * dk[tx] : 0.f)
                - ((j != 0) ? a * tInv[tx][jj] : 0.f);
        tV[jj][tx] = v;
    }
    __syncthreads();
    #pragma unroll
    for (int s = 0; s < 4; s++) {
        int kk = ty + 8*s;
        out_a[(size_t)b*KTOK*(KTOK+1) + (size_t)(k0 + kk)*(KTOK+1) + (j0 + tx) + 1]
            = tV[tx][kk];
    }
}

__global__ void d0_kernel(const float* __restrict__ fid,
                          const float* __restrict__ Inv,
                          float* __restrict__ out_a) {
    int i = blockIdx.x * blockDim.x + threadIdx.x;
    if (i >= BATCH*KTOK) return;
    int b = i / KTOK, k = i % KTOK;
    out_a[(size_t)b*KTOK*(KTOK+1) + (size_t)k*(KTOK+1)]
        = fid[i] * Inv[(size_t)b*KTOK*KTOK + (size_t)k*KTOK];
}

// si[b,j,c] += a_ki[b,j,0] * exparam[c]   (into packed esc s-section)
__global__ void rank1_kernel(const float* __restrict__ out_a,
                             const float* __restrict__ exparam,
                             float* __restrict__ esc) {
    int i = blockIdx.x * blockDim.x + threadIdx.x;
    if (i >= BATCH*KTOK*SEM) return;
    int c  = i % SEM;
    int bj = i / SEM;
    float a0 = out_a[(size_t)bj*(KTOK+1)];
    esc[(size_t)bj*ESCW + SEM + c] += a0 * exparam[c];
}

// ---------------- 128x128x16 cp.async double-buffered fp32 GEMM ----------------
// Requires: M % 128 == 0, N % 128 == 0, K % 16 == 0 (true for all call sites).
#define FLAG_BIAS  1
#define FLAG_TANH  2

__global__ __launch_bounds__(256, 2)
void gemm_kernel(const float* __restrict__ A, const float* __restrict__ B,
                 float* __restrict__ C, const float* __restrict__ bias,
                 int M, int N, int Kd,
                 long long sAb, int sAm, int sAk,
                 long long sBb, int sBk, int sBn,
                 long long sCb, int sCm, int sBiasB,
                 float alpha, float beta, int flags) {
    __shared__ float As[2][16][132];
    __shared__ float Bs[2][16][132];
    int bz = blockIdx.z;
    A += (size_t)bz * sAb;
    B += (size_t)bz * sBb;
    C += (size_t)bz * sCb;
    if (bias) bias += (size_t)bz * sBiasB;
    int m0 = blockIdx.y * 128, n0 = blockIdx.x * 128;
    int tid = threadIdx.x;
    int tx = tid & 15, ty = tid >> 4;

    const bool aK = (sAk == 1);   // A contiguous in K
    const bool bN = (sBn == 1);   // B contiguous in N
    const float* ga;
    const float* gb;
    long long gaStep, gbStep;
    int aR, aC, bR, bC;
    if (aK) { aC = tid >> 1; aR = (tid & 1) * 8;
              ga = A + (size_t)(m0 + aC) * sAm + aR; gaStep = 16; }
    else    { aR = tid >> 4; aC = (tid & 15) * 8;
              ga = A + (size_t)(m0 + aC) * sAm + (size_t)aR * sAk;
              gaStep = (long long)16 * sAk; }
    if (bN) { bR = tid >> 4; bC = (tid & 15) * 8;
              gb = B + (size_t)bR * sBk + (n0 + bC); gbStep = (long long)16 * sBk; }
    else    { bC = tid >> 1; bR = (tid & 1) * 8;
              gb = B + (size_t)(n0 + bC) * sBn + (size_t)bR * sBk;
              gbStep = (long long)16 * sBk; }

    auto issue = [&](int buf) {
        if (aK) {
            uint32_t s = smem_u32(&As[buf][aR][aC]);
            #pragma unroll
            for (int i = 0; i < 8; i++) cp_async4(s + i * 132 * 4, ga + i);
        } else {
            uint32_t s = smem_u32(&As[buf][aR][aC]);
            #pragma unroll
            for (int i = 0; i < 8; i++) cp_async4(s + i * 4, ga + (size_t)i * sAm);
        }
        if (bN) {
            uint32_t s = smem_u32(&Bs[buf][bR][bC]);
            cp_async16(s, gb);
            cp_async16(s + 16, gb + 4);
        } else {
            uint32_t s = smem_u32(&Bs[buf][bR][bC]);
            #pragma unroll
            for (int i = 0; i < 8; i++) cp_async4(s + i * 132 * 4, gb + (size_t)i * sBk);
        }
        ga += gaStep; gb += gbStep;
        cp_commit();
    };

    float acc[8][8];
    #pragma unroll
    for (int i = 0; i < 8; i++)
        #pragma unroll
        for (int j = 0; j < 8; j++) acc[i][j] = 0.f;

    int nk = Kd >> 4;
    issue(0);
    for (int kt = 0; kt < nk; kt++) {
        int cur = kt & 1;
        if (kt + 1 < nk) { issue(cur ^ 1); cp_wait<1>(); }
        else             { cp_wait<0>(); }
        __syncthreads();
        #pragma unroll
        for (int kk = 0; kk < 16; kk++) {
            float4 a0 = *(const float4*)&As[cur][kk][ty*8];
            float4 a1 = *(const float4*)&As[cur][kk][ty*8 + 4];
            float4 b0 = *(const float4*)&Bs[cur][kk][tx*8];
            float4 b1 = *(const float4*)&Bs[cur][kk][tx*8 + 4];
            float av[8] = {a0.x, a0.y, a0.z, a0.w, a1.x, a1.y, a1.z, a1.w};
            float bv[8] = {b0.x, b0.y, b0.z, b0.w, b1.x, b1.y, b1.z, b1.w};
            #pragma unroll
            for (int i = 0; i < 8; i++)
                #pragma unroll
                for (int j = 0; j < 8; j++)
                    acc[i][j] += av[i] * bv[j];
        }
        __syncthreads();
    }

    // ---- epilogue ----
    #pragma unroll
    for (int i = 0; i < 8; i++) {
        float* cp = C + (size_t)(m0 + ty*8 + i) * sCm + n0 + tx*8;
        #pragma unroll
        for (int g = 0; g < 2; g++) {
            float v0 = alpha * acc[i][4*g + 0];
            float v1 = alpha * acc[i][4*g + 1];
            float v2 = alpha * acc[i][4*g + 2];
            float v3 = alpha * acc[i][4*g + 3];
            if (beta != 0.f) {
                float4 o = *(const float4*)(cp + 4*g);
                v0 += beta * o.x; v1 += beta * o.y;
                v2 += beta * o.z; v3 += beta * o.w;
            }
            if (flags & FLAG_BIAS) {
                const float* bb = bias + n0 + tx*8 + 4*g;
                v0 += bb[0]; v1 += bb[1]; v2 += bb[2]; v3 += bb[3];
            }
            if (flags & FLAG_TANH) {
                v0 = tanhf(v0); v1 = tanhf(v1);
                v2 = tanhf(v2); v3 = tanhf(v3);
            }
            float4 w; w.x = v0; w.y = v1; w.z = v2; w.w = v3;
            *(float4*)(cp + 4*g) = w;
        }
    }
}

static inline void launch_gemm(const float* A, const float* B, float* C,
                               const float* bias,
                               int M, int N, int Kd,
                               long long sAb, int sAm, int sAk,
                               long long sBb, int sBk, int sBn,
                               long long sCb, int sCm, int sBiasB,
                               float alpha, float beta, int flags, int batch) {
    dim3 g(N / 128, M / 128, batch);
    gemm_kernel<<<g, 256>>>(A, B, C, bias, M, N, Kd,
                            sAb, sAm, sAk, sBb, sBk, sBn, sCb, sCm, sBiasB,
                            alpha, beta, flags);
}

// ---------------- driver ----------------
extern "C" void kernel_launch(void* const* d_in, const int* in_sizes, int n_in,
                              void* d_out, int out_size) {
    const float* x       = (const float*)d_in[0];
    const float* Wp_w    = (const float*)d_in[1];
    const float* Wp_b    = (const float*)d_in[2];
    const float* Wc_w    = (const float*)d_in[3];
    const float* Wc_b    = (const float*)d_in[4];
    const float* fi_w    = (const float*)d_in[5];
    const float* Wa_w    = (const float*)d_in[6];
    const float* exparam = (const float*)d_in[7];
    const float* Wr_w    = (const float*)d_in[8];
    const float* Wr_b    = (const float*)d_in[9];

    float* out_r = (float*)d_out;
    float* out_a = out_r + (size_t)BATCH*KTOK*SEM;

    float *esc, *di, *ujk, *vv, *Am, *gg, *cm, *fid, *cs, *pmax, *psum;
    float *G, *Wf, *Pvf, *Rf, *Wcat, *bcat;
    cudaGetSymbolAddress((void**)&esc,  g_esc);
    cudaGetSymbolAddress((void**)&di,   g_di);
    cudaGetSymbolAddress((void**)&ujk,  g_ujk);
    cudaGetSymbolAddress((void**)&vv,   g_v);
    cudaGetSymbolAddress((void**)&Am,   g_A);
    cudaGetSymbolAddress((void**)&gg,   g_g);
    cudaGetSymbolAddress((void**)&cm,   g_cm);
    cudaGetSymbolAddress((void**)&fid,  g_fid);
    cudaGetSymbolAddress((void**)&cs,   g_cs);
    cudaGetSymbolAddress((void**)&pmax, g_pmax);
    cudaGetSymbolAddress((void**)&psum, g_psum);
    cudaGetSymbolAddress((void**)&G,    g_G);
    cudaGetSymbolAddress((void**)&Wf,   g_Wf);
    cudaGetSymbolAddress((void**)&Pvf,  g_Pvf);
    cudaGetSymbolAddress((void**)&Rf,   g_Rf);
    cudaGetSymbolAddress((void**)&Wcat, g_Wcat);
    cudaGetSymbolAddress((void**)&bcat, g_bcat);

    float* uj = ujk;
    float* uk = ujk + (size_t)BATCH*KTOK*STRD;

    cudaFuncSetAttribute(pivot_inv_kernel,
                         cudaFuncAttributeMaxDynamicSharedMemorySize,
                         (NB*(NB+1) + NB) * 8);

    // 1) semantic/structural split (e into packed esc), weight concat
    split_kernel<<<(BATCH*KTOK*SEM + 255)/256, 256>>>(x, esc, di);
    wcat_kernel<<<(STRD*STRD + 255)/256, 256>>>(Wp_w, Wp_b, Wc_w, Wc_b, Wcat, bcat);

    // 2) [u_j; u_k] = tanh(d @ [Wp; Wc] + [bp; bc])  — one batch=2 GEMM
    launch_gemm(di, Wcat, ujk, bcat, BATCH*KTOK, STRD, STRD,
                0, STRD, 1,
                (long long)STRD*STRD, STRD, 1,
                (long long)BATCH*KTOK*STRD, STRD, STRD,
                1.f, 0.f, FLAG_BIAS|FLAG_TANH, 2);

    // 3) v = u_k @ Wa^T
    launch_gemm(uk, Wa_w, vv, nullptr, BATCH*KTOK, STRD, STRD,
                0, STRD, 1, 0, 1, STRD, 0, STRD, 0, 1.f, 0.f, 0, 1);

    // 4) raw root scores g = d @ fi_w
    fi_kernel<<<(BATCH*KTOK + 7)/8, 256>>>(di, fi_w, gg);

    // 5) raw bilinear scores S = u_j v^T  (batched NT GEMM)
    launch_gemm(uj, vv, Am, nullptr, KTOK, KTOK, STRD,
                (long long)KTOK*STRD, STRD, 1,
                (long long)KTOK*STRD, 1, STRD,
                (long long)KTOK*KTOK, KTOK, 0, 1.f, 0.f, 0, BATCH);

    // 6) parallel two-phase column max / exp-normalize / column sums
    {
        dim3 gp((BATCH*KTOK + 255)/256, JP);
        colmax_part_kernel<<<gp, 256>>>(Am, pmax);
        colmax_reduce_kernel<<<(BATCH*KTOK + 255)/256, 256>>>(pmax, gg, cm, fid);
        normA_colsum_part_kernel<<<gp, 256>>>(Am, cm, psum);
        colsum_reduce_kernel<<<(BATCH*KTOK + 255)/256, 256>>>(psum, cs);
    }

    // 7) Laplacian (fp32) into G
    build_kernel<<<(unsigned)(((size_t)BATCH*KTOK*KTOK + 255)/256), 256>>>(Am, fid, cs, G);

    // 8) in-place blocked Gauss-Jordan: G -> G^{-1}  (fp64 pivot blocks)
    for (int s = 0; s < NSTEP; s++) {
        int k0 = s * NB;
        pivot_inv_kernel<<<BATCH, 512, (NB*(NB+1) + NB) * 8>>>(G, Pvf, k0);
        copyw_kernel<<<(BATCH*KTOK*NB + 255)/256, 256>>>(G, Wf, k0);
        // R = Pinv @ G[J, :]   (NB x KTOK)
        launch_gemm(Pvf, G + (size_t)k0*KTOK, Rf, nullptr, NB, KTOK, NB,
                    (long long)NB*NB, NB, 1,
                    (long long)KTOK*KTOK, KTOK, 1,
                    (long long)NB*KTOK, KTOK, 0, 1.f, 0.f, 0, BATCH);
        // G -= W @ R           (KTOK x KTOK)
        launch_gemm(Wf, Rf, G, nullptr, KTOK, KTOK, NB,
                    (long long)KTOK*NB, NB, 1,
                    (long long)NB*KTOK, KTOK, 1,
                    (long long)KTOK*KTOK, KTOK, 0, -1.f, 1.f, 0, BATCH);
    }

    // 9) edge marginals -> out_a (transposed), root column d0
    marginals_kernel<<<dim3(KTOK/32, KTOK/32, BATCH), dim3(32, 8)>>>(Am, G, out_a);
    d0_kernel<<<(BATCH*KTOK + 255)/256, 256>>>(fid, G, out_a);

    // 10) s-section of esc: si = a_ki[:,:,1:] @ e + a_ki[:,:,0] x exparam
    launch_gemm(out_a + 1, esc, esc + SEM, nullptr, KTOK, SEM, KTOK,
                (long long)KTOK*(KTOK+1), KTOK+1, 1,
                (long long)KTOK*ESCW, ESCW, 1,
                (long long)KTOK*ESCW, ESCW, 0, 1.f, 0.f, 0, BATCH);
    rank1_kernel<<<(BATCH*KTOK*SEM + 255)/256, 256>>>(out_a, exparam, esc);

    // 11) c-section of esc: ci = a_ik @ e  (a_ik read as transpose of out_a[:,:,1:])
    launch_gemm(out_a + 1, esc, esc + 2*SEM, nullptr, KTOK, SEM, KTOK,
                (long long)KTOK*(KTOK+1), 1, KTOK+1,
                (long long)KTOK*ESCW, ESCW, 1,
                (long long)KTOK*ESCW, ESCW, 0, 1.f, 0.f, 0, BATCH);

    // 12) r = tanh(esc @ Wr + b)  — ONE fused K=1152 GEMM
    launch_gemm(esc, Wr_w, out_r, Wr_b, BATCH*KTOK, SEM, ESCW,
                0, ESCW, 1, 0, SEM, 1, 0, SEM, 0,
                1.f, 0.f, FLAG_BIAS|FLAG_TANH, 1);
}